// round 13
// baseline (speedup 1.0000x reference)
#include <cuda_runtime.h>
#include <cfloat>
#include <cstddef>
#include <cstdint>

#define HID   768
#define INTER 3072
#define NH    12
#define DH    64
#define NTOK  16384
#define WIN   256
#define CH    256
#define MIDW  (3*HID + INTER)   // 5376
#define QKVW  (3*HID)           // 2304
#define COMBW (HID + INTER)     // 3840

#define ASTR 36                       // gemm smem row stride in floats (pad 4)
#define TILE_BYTES (128 * ASTR * 4)   // 18432 per operand tile
#define STAGE_BYTES (2 * TILE_BYTES)  // A + B = 36864
#define GSTAGES 3
#define DSMEM_BYTES (GSTAGES * STAGE_BYTES) // 110592; 2 CTAs/SM = 216 KB
#define PGRID 296                     // persistent grid: 2 CTAs x 148 SMs

#define AQ   68                       // attn Q/K/V smem row stride (floats)
#define PSTR 36                       // attn probs smem row stride
#define ATTN_SMEM ((128*AQ + 32*AQ + 32*AQ) * 4)   // 52224 B

// Scratch (device globals: allocation inside kernel_launch is forbidden)
__device__ float g_xn  [(size_t)NTOK * HID];     //  50 MB
__device__ float g_comb[(size_t)NTOK * COMBW];   // 252 MB
__device__ float g_wt1 [(size_t)MIDW * HID];     //  16.5 MB
__device__ float g_wt2 [(size_t)HID * COMBW];    //  11.8 MB
__device__ float g_qr  [(size_t)NH * NTOK * DH]; //  50 MB  RoPE'd+scaled Q [h][tok][d]
__device__ float g_kr  [(size_t)NH * NTOK * DH]; //  50 MB  RoPE'd K
__device__ float g_vr  [(size_t)NH * NTOK * DH]; //  50 MB  V

// ---------------------------------------------------------------- helpers
__device__ __forceinline__ uint32_t smem_u32(const void* p) {
    uint32_t a;
    asm("{ .reg .u64 t; cvta.to.shared.u64 t, %1; cvt.u32.u64 %0, t; }"
        : "=r"(a) : "l"(p));
    return a;
}
__device__ __forceinline__ float f2tf32_rna(float x) {
    uint32_t u;
    asm("cvt.rna.tf32.f32 %0, %1;" : "=r"(u) : "f"(x));
    return __uint_as_float(u);
}
__device__ __forceinline__ void cp_async16(uint32_t dst, const void* src) {
    asm volatile("cp.async.cg.shared.global [%0], [%1], 16;"
                 :: "r"(dst), "l"(src) : "memory");
}
__device__ __forceinline__ void cp_commit() {
    asm volatile("cp.async.commit_group;" ::: "memory");
}
__device__ __forceinline__ void cp_wait1() {
    asm volatile("cp.async.wait_group 1;" ::: "memory");
}
__device__ __forceinline__ void cp_wait0() {
    asm volatile("cp.async.wait_group 0;" ::: "memory");
}
__device__ __forceinline__ uint32_t lds32(uint32_t addr) {
    uint32_t v;
    asm volatile("ld.shared.b32 %0, [%1];" : "=r"(v) : "r"(addr));
    return v;
}
__device__ __forceinline__ void mma_tf32(float* d, const uint32_t* a, const uint32_t* b) {
    asm volatile(
        "mma.sync.aligned.m16n8k8.row.col.f32.tf32.tf32.f32 "
        "{%0,%1,%2,%3}, {%4,%5,%6,%7}, {%8,%9}, {%0,%1,%2,%3};"
        : "+f"(d[0]), "+f"(d[1]), "+f"(d[2]), "+f"(d[3])
        : "r"(a[0]), "r"(a[1]), "r"(a[2]), "r"(a[3]), "r"(b[0]), "r"(b[1]));
}

// ---------------------------------------------------------------- GELU (tanh approx = jax default)
__device__ __forceinline__ float gelu_f(float x) {
    float x3 = x * x * x;
    return 0.5f * x * (1.0f + tanhf(0.7978845608028654f * (x + 0.044715f * x3)));
}

// ---------------------------------------------------------------- LayerNorm
__global__ void ln_kernel(const float* __restrict__ x,
                          const float* __restrict__ gam,
                          const float* __restrict__ bet)
{
    int row = blockIdx.x;
    int t   = threadIdx.x;
    const float* xr = x + (size_t)row * HID;
    float v0 = xr[t], v1 = xr[t + 256], v2 = xr[t + 512];
    float s  = v0 + v1 + v2;
    float s2 = v0*v0 + v1*v1 + v2*v2;
    #pragma unroll
    for (int o = 16; o > 0; o >>= 1) {
        s  += __shfl_xor_sync(0xffffffffu, s,  o);
        s2 += __shfl_xor_sync(0xffffffffu, s2, o);
    }
    __shared__ float red0[8], red1[8];
    __shared__ float stat[2];
    int w = t >> 5, l = t & 31;
    if (l == 0) { red0[w] = s; red1[w] = s2; }
    __syncthreads();
    if (t == 0) {
        float ts = 0.f, ts2 = 0.f;
        #pragma unroll
        for (int i = 0; i < 8; i++) { ts += red0[i]; ts2 += red1[i]; }
        float mu  = ts * (1.0f / HID);
        float var = ts2 * (1.0f / HID) - mu * mu;
        stat[0] = mu;
        stat[1] = rsqrtf(var + 1e-5f);
    }
    __syncthreads();
    float mu = stat[0], inv = stat[1];
    float* o = g_xn + (size_t)row * HID;
    o[t]       = (v0 - mu) * inv * gam[t]       + bet[t];
    o[t + 256] = (v1 - mu) * inv * gam[t + 256] + bet[t + 256];
    o[t + 512] = (v2 - mu) * inv * gam[t + 512] + bet[t + 512];
}

// ---------------------------------------------------------------- Transpose (R x C -> C x R), dims % 32 == 0
__global__ void transpose_kernel(const float* __restrict__ in, float* __restrict__ out,
                                 int R, int C)
{
    __shared__ float tile[32][33];
    int bx = blockIdx.x * 32, by = blockIdx.y * 32;
    int tx = threadIdx.x, ty = threadIdx.y;
    #pragma unroll
    for (int i = 0; i < 32; i += 8)
        tile[ty + i][tx] = in[(size_t)(by + ty + i) * C + bx + tx];
    __syncthreads();
    #pragma unroll
    for (int i = 0; i < 32; i += 8)
        out[(size_t)(bx + ty + i) * R + by + tx] = f2tf32_rna(tile[tx][ty + i]);
}

// ---------------------------------------------------------------- HMMA tf32 GEMM (persistent)
// 128x128 CTA tile, 4 warps, 64x64 warp tile, 3-stage cp.async ring.
// Persistent: grid=PGRID, loops tiles. tile -> (bn = tile%ntx, bm = tile/ntx).
// epi: 0 = bias (+R residual) -> C ; 1 = gelu(bias) -> C ;
//      2 = QKV mode: RoPE+scale -> g_qr/g_kr/g_vr (C unused)
__global__ __launch_bounds__(128, 2)
void tgemm_kernel(const float* __restrict__ A, int lda,
                  const float* __restrict__ Bt, int ldb,
                  const float* __restrict__ bias,
                  const float* __restrict__ R,
                  float* __restrict__ C, int ldc,
                  int K, int epi, int ntx, int ntiles,
                  const float* __restrict__ psin,
                  const float* __restrict__ pcos)
{
    extern __shared__ float sm[];
    uint32_t sbase = smem_u32(sm);

    int t = threadIdx.x;
    int wid = t >> 5, lane = t & 31;
    int warp_m = (wid >> 1) * 64, warp_n = (wid & 1) * 64;
    int r = lane >> 2, c = lane & 3;

    int cm[8], ck[8];
    #pragma unroll
    for (int i = 0; i < 8; i++) {
        int id = t + i * 128;
        cm[i] = id >> 3;
        ck[i] = (id & 7) * 4;
    }

    int S = K / 32;

    for (int tile = blockIdx.x; tile < ntiles; tile += gridDim.x) {
        int bn = (tile % ntx) * 128;
        int bm = (tile / ntx) * 128;
        const float* Ag = A  + (size_t)bm * lda;
        const float* Bg = Bt + (size_t)bn * ldb;

        float acc[32][4];
        #pragma unroll
        for (int i = 0; i < 32; i++)
            #pragma unroll
            for (int j = 0; j < 4; j++) acc[i][j] = 0.f;

        auto load_stage = [&](int buf, int kbase) {
            uint32_t ab = sbase + (uint32_t)buf * STAGE_BYTES;
            uint32_t bb = ab + TILE_BYTES;
            #pragma unroll
            for (int i = 0; i < 8; i++) {
                cp_async16(ab + (uint32_t)(cm[i] * ASTR + ck[i]) * 4u,
                           Ag + (size_t)cm[i] * lda + kbase + ck[i]);
                cp_async16(bb + (uint32_t)(cm[i] * ASTR + ck[i]) * 4u,
                           Bg + (size_t)cm[i] * ldb + kbase + ck[i]);
            }
        };

        __syncthreads();   // smem ring reuse across tiles
        load_stage(0, 0);
        cp_commit();
        load_stage(1, 32);
        cp_commit();

        int buf = 0;
        for (int s = 0; s < S; s++) {
            if (s + 1 < S) cp_wait1();
            else           cp_wait0();
            __syncthreads();
            int nxt = s + 2;
            if (nxt < S) {
                int nbuf = buf + 2; if (nbuf >= GSTAGES) nbuf -= GSTAGES;
                load_stage(nbuf, nxt * 32);
                cp_commit();
            }

            uint32_t ab = sbase + (uint32_t)buf * STAGE_BYTES;
            uint32_t bb = ab + TILE_BYTES;
            #pragma unroll
            for (int ks = 0; ks < 4; ks++) {
                int k0 = ks * 8;
                uint32_t af[4][4];
                #pragma unroll
                for (int mt = 0; mt < 4; mt++) {
                    uint32_t base = ab + (uint32_t)((warp_m + mt * 16 + r) * ASTR + k0 + c) * 4u;
                    af[mt][0] = lds32(base);
                    af[mt][1] = lds32(base + 8u * ASTR * 4u);
                    af[mt][2] = lds32(base + 16u);
                    af[mt][3] = lds32(base + 8u * ASTR * 4u + 16u);
                }
                uint32_t bf[8][2];
                #pragma unroll
                for (int nt = 0; nt < 8; nt++) {
                    uint32_t base = bb + (uint32_t)((warp_n + nt * 8 + r) * ASTR + k0 + c) * 4u;
                    bf[nt][0] = lds32(base);
                    bf[nt][1] = lds32(base + 16u);
                }
                #pragma unroll
                for (int mt = 0; mt < 4; mt++)
                    #pragma unroll
                    for (int nt = 0; nt < 8; nt++)
                        mma_tf32(acc[mt * 8 + nt], af[mt], bf[nt]);
            }
            if (++buf == GSTAGES) buf = 0;
        }

        // ---- epilogue ----
        #pragma unroll
        for (int mt = 0; mt < 4; mt++) {
            #pragma unroll
            for (int nt = 0; nt < 8; nt++) {
                float* a4 = acc[mt * 8 + nt];
                int gm0 = bm + warp_m + mt * 16 + r;
                int gn  = bn + warp_n + nt * 8 + c * 2;
                float bx = bias[gn], by = bias[gn + 1];
                #pragma unroll
                for (int half = 0; half < 2; half++) {
                    int gm = gm0 + half * 8;
                    float vx = a4[half * 2 + 0] + bx;
                    float vy = a4[half * 2 + 1] + by;
                    if (epi == 2) {
                        // QKV: RoPE (+0.125 scale for q), tf32-round, scatter
                        int sec = gn / HID;            // 0=q 1=k 2=v
                        int rem = gn - sec * HID;
                        int h = rem >> 6, d = rem & 63;
                        size_t off = ((size_t)h * NTOK + gm) * DH + d;
                        if (sec == 2) {
                            *(float2*)(g_vr + off) =
                                make_float2(f2tf32_rna(vx), f2tf32_rna(vy));
                        } else {
                            float2 sv = *(const float2*)(psin + (size_t)gm * DH + d);
                            float2 cv = *(const float2*)(pcos + (size_t)gm * DH + d);
                            float ox = vx * cv.x - vy * sv.x;
                            float oy = vy * cv.y + vx * sv.y;
                            if (sec == 0) {
                                ox *= 0.125f; oy *= 0.125f;
                                *(float2*)(g_qr + off) =
                                    make_float2(f2tf32_rna(ox), f2tf32_rna(oy));
                            } else {
                                *(float2*)(g_kr + off) =
                                    make_float2(f2tf32_rna(ox), f2tf32_rna(oy));
                            }
                        }
                    } else {
                        if (R) {
                            const float* rp = R + (size_t)gm * ldc + gn;
                            vx += rp[0]; vy += rp[1];
                        }
                        if (epi == 1) { vx = gelu_f(vx); vy = gelu_f(vy); }
                        *(float2*)(C + (size_t)gm * ldc + gn) = make_float2(vx, vy);
                    }
                }
            }
        }
    }
}

// ---------------------------------------------------------------- Attention (flash, mma.sync tf32; unchanged from R11)
__global__ __launch_bounds__(256, 2)
void attn_kernel(const int* __restrict__ lenp)
{
    extern __shared__ float sma[];
    float* Qs = sma;
    float* Ks = sma + 128 * AQ;
    float* Vs = Ks + 32 * AQ;
    float* Ps = Qs;

    int blk = blockIdx.x, h = blockIdx.y;
    int t = threadIdx.x, wid = t >> 5, lane = t & 31;
    int r = lane >> 2, cc = lane & 3;
    int q0  = blk * 128;
    int q0w = q0 + wid * 16;
    unsigned lm = ~((unsigned)(*lenp) - 1u);
    int qlo = q0w + r, qhi = qlo + 8;
    unsigned seqlo = (unsigned)qlo & lm, seqhi = (unsigned)qhi & lm;

    const float* Qg = g_qr + ((size_t)h * NTOK + q0) * DH;
    const float* Kg = g_kr + (size_t)h * NTOK * DH;
    const float* Vg = g_vr + (size_t)h * NTOK * DH;

    #pragma unroll
    for (int i = 0; i < 8; i++) {
        int f = t + i * 256;
        int row = f >> 4, c4 = f & 15;
        *(float4*)&Qs[row * AQ + c4 * 4] = *(const float4*)(Qg + (size_t)row * DH + c4 * 4);
    }
    __syncthreads();

    uint32_t qf[8][4];
    #pragma unroll
    for (int ks = 0; ks < 8; ks++) {
        const float* base = &Qs[(wid * 16 + r) * AQ + ks * 8 + cc];
        qf[ks][0] = __float_as_uint(base[0]);
        qf[ks][1] = __float_as_uint(base[8 * AQ]);
        qf[ks][2] = __float_as_uint(base[4]);
        qf[ks][3] = __float_as_uint(base[8 * AQ + 4]);
    }

    float o[8][4];
    #pragma unroll
    for (int i = 0; i < 8; i++)
        #pragma unroll
        for (int j = 0; j < 4; j++) o[i][j] = 0.f;
    float m_lo = -1e30f, m_hi = -1e30f, l_lo = 0.f, l_hi = 0.f;

    int kt0 = (q0 < 256) ? ((256 - q0) >> 5) : 0;

    for (int kt = kt0; kt < 12; kt++) {
        int kbase = q0 - 256 + kt * 32;
        __syncthreads();
        #pragma unroll
        for (int i = 0; i < 2; i++) {
            int f = t + i * 256;
            int row = f >> 4, c4 = f & 15;
            *(float4*)&Ks[row * AQ + c4 * 4] = *(const float4*)(Kg + (size_t)(kbase + row) * DH + c4 * 4);
            *(float4*)&Vs[row * AQ + c4 * 4] = *(const float4*)(Vg + (size_t)(kbase + row) * DH + c4 * 4);
        }
        __syncthreads();

        bool active = (kbase <= q0w + 15) && (q0w - (kbase + 31) < WIN);
        if (active) {
            float sc[4][4];
            #pragma unroll
            for (int nt = 0; nt < 4; nt++) {
                sc[nt][0] = sc[nt][1] = sc[nt][2] = sc[nt][3] = 0.f;
                #pragma unroll
                for (int ks = 0; ks < 8; ks++) {
                    const float* bb = &Ks[(nt * 8 + r) * AQ + ks * 8 + cc];
                    uint32_t bf[2] = { __float_as_uint(bb[0]), __float_as_uint(bb[4]) };
                    mma_tf32(sc[nt], qf[ks], bf);
                }
            }
            float tlo = -1e30f, thi = -1e30f;
            #pragma unroll
            for (int nt = 0; nt < 4; nt++) {
                #pragma unroll
                for (int b = 0; b < 2; b++) {
                    int ktok = kbase + nt * 8 + 2 * cc + b;
                    unsigned kseq = (unsigned)ktok & lm;
                    int dlo = qlo - ktok, dhi = qhi - ktok;
                    if (!(dlo >= 0 && dlo < WIN && kseq == seqlo)) sc[nt][b]     = -2e30f;
                    if (!(dhi >= 0 && dhi < WIN && kseq == seqhi)) sc[nt][2 + b] = -2e30f;
                    tlo = fmaxf(tlo, sc[nt][b]);
                    thi = fmaxf(thi, sc[nt][2 + b]);
                }
            }
            tlo = fmaxf(tlo, __shfl_xor_sync(0xffffffffu, tlo, 1));
            tlo = fmaxf(tlo, __shfl_xor_sync(0xffffffffu, tlo, 2));
            thi = fmaxf(thi, __shfl_xor_sync(0xffffffffu, thi, 1));
            thi = fmaxf(thi, __shfl_xor_sync(0xffffffffu, thi, 2));

            float mn_lo = fmaxf(m_lo, tlo), mn_hi = fmaxf(m_hi, thi);
            float co_lo = __expf(m_lo - mn_lo), co_hi = __expf(m_hi - mn_hi);
            m_lo = mn_lo; m_hi = mn_hi;
            l_lo *= co_lo; l_hi *= co_hi;
            #pragma unroll
            for (int i = 0; i < 8; i++) {
                o[i][0] *= co_lo; o[i][1] *= co_lo;
                o[i][2] *= co_hi; o[i][3] *= co_hi;
            }
            float* Pw = Ps + wid * 16 * PSTR;
            #pragma unroll
            for (int nt = 0; nt < 4; nt++) {
                float p0 = f2tf32_rna(__expf(sc[nt][0] - mn_lo));
                float p1 = f2tf32_rna(__expf(sc[nt][1] - mn_lo));
                float p2 = f2tf32_rna(__expf(sc[nt][2] - mn_hi));
                float p3 = f2tf32_rna(__expf(sc[nt][3] - mn_hi));
                l_lo += p0 + p1; l_hi += p2 + p3;
                Pw[r * PSTR + nt * 8 + 2 * cc]           = p0;
                Pw[r * PSTR + nt * 8 + 2 * cc + 1]       = p1;
                Pw[(r + 8) * PSTR + nt * 8 + 2 * cc]     = p2;
                Pw[(r + 8) * PSTR + nt * 8 + 2 * cc + 1] = p3;
            }
            __syncwarp();
            uint32_t pf[4][4];
            #pragma unroll
            for (int kk = 0; kk < 4; kk++) {
                const float* base = &Pw[r * PSTR + kk * 8 + cc];
                pf[kk][0] = __float_as_uint(base[0]);
                pf[kk][1] = __float_as_uint(base[8 * PSTR]);
                pf[kk][2] = __float_as_uint(base[4]);
                pf[kk][3] = __float_as_uint(base[8 * PSTR + 4]);
            }
            #pragma unroll
            for (int ntd = 0; ntd < 8; ntd++) {
                #pragma unroll
                for (int kk = 0; kk < 4; kk++) {
                    uint32_t bf[2] = {
                        __float_as_uint(Vs[(kk * 8 + cc) * AQ + ntd * 8 + r]),
                        __float_as_uint(Vs[(kk * 8 + cc + 4) * AQ + ntd * 8 + r]) };
                    mma_tf32(o[ntd], pf[kk], bf);
                }
            }
        }
    }

    l_lo += __shfl_xor_sync(0xffffffffu, l_lo, 1);
    l_lo += __shfl_xor_sync(0xffffffffu, l_lo, 2);
    l_hi += __shfl_xor_sync(0xffffffffu, l_hi, 1);
    l_hi += __shfl_xor_sync(0xffffffffu, l_hi, 2);
    float ilo = 1.0f / l_lo, ihi = 1.0f / l_hi;
    float* out_lo = g_comb + (size_t)qlo * COMBW + h * DH;
    float* out_hi = g_comb + (size_t)qhi * COMBW + h * DH;
    #pragma unroll
    for (int ntd = 0; ntd < 8; ntd++) {
        int gn = ntd * 8 + 2 * cc;
        *(float2*)(out_lo + gn) = make_float2(o[ntd][0] * ilo, o[ntd][1] * ilo);
        *(float2*)(out_hi + gn) = make_float2(o[ntd][2] * ihi, o[ntd][3] * ihi);
    }
}

// ---------------------------------------------------------------- launch
extern "C" void kernel_launch(void* const* d_in, const int* in_sizes, int n_in,
                              void* d_out, int out_size)
{
    (void)in_sizes; (void)n_in; (void)out_size;
    const float* x        = (const float*)d_in[0];
    const float* pos_sin  = (const float*)d_in[2];
    const float* pos_cos  = (const float*)d_in[3];
    const float* ln_scale = (const float*)d_in[4];
    const float* ln_off   = (const float*)d_in[5];
    const float* w_in     = (const float*)d_in[6];
    const float* b_in     = (const float*)d_in[7];
    const float* w_out    = (const float*)d_in[8];
    const float* b_out    = (const float*)d_in[9];
    const int*   lenp     = (const int*)d_in[10];
    float* out = (float*)d_out;

    static float *p_xn = nullptr, *p_comb = nullptr,
                 *p_wt1 = nullptr, *p_wt2 = nullptr;
    static cudaStream_t s1 = nullptr;
    static cudaEvent_t e0 = nullptr, eT = nullptr, eLN = nullptr, eF = nullptr;
    if (!p_xn) {
        cudaGetSymbolAddress((void**)&p_xn,   g_xn);
        cudaGetSymbolAddress((void**)&p_comb, g_comb);
        cudaGetSymbolAddress((void**)&p_wt1,  g_wt1);
        cudaGetSymbolAddress((void**)&p_wt2,  g_wt2);
        cudaFuncSetAttribute(tgemm_kernel,
                             cudaFuncAttributeMaxDynamicSharedMemorySize, DSMEM_BYTES);
        cudaFuncSetAttribute(attn_kernel,
                             cudaFuncAttributeMaxDynamicSharedMemorySize, ATTN_SMEM);
        cudaStreamCreateWithFlags(&s1, cudaStreamNonBlocking);
        cudaEventCreateWithFlags(&e0,  cudaEventDisableTiming);
        cudaEventCreateWithFlags(&eT,  cudaEventDisableTiming);
        cudaEventCreateWithFlags(&eLN, cudaEventDisableTiming);
        cudaEventCreateWithFlags(&eF,  cudaEventDisableTiming);
    }

    // fork s1 from the (captured) default stream
    cudaEventRecord(e0, 0);
    cudaStreamWaitEvent(s1, e0, 0);

    // s1: weight transposes (+tf32 round); s0: layernorm
    transpose_kernel<<<dim3(MIDW / 32, HID / 32),   dim3(32, 8), 0, s1>>>(w_in,  p_wt1, HID,   MIDW);
    transpose_kernel<<<dim3(HID / 32,  COMBW / 32), dim3(32, 8), 0, s1>>>(w_out, p_wt2, COMBW, HID);
    ln_kernel<<<NTOK, 256>>>(x, ln_scale, ln_off);
    cudaEventRecord(eLN, 0);

    // s0: QKV GEMM with fused RoPE epilogue -> g_qr/g_kr/g_vr (needs wt1)
    cudaEventRecord(eT, s1);
    cudaStreamWaitEvent(0, eT, 0);
    tgemm_kernel<<<PGRID, 128, DSMEM_BYTES>>>(
        p_xn, HID, p_wt1, HID, b_in, nullptr, nullptr, 0,
        HID, 2, QKVW / 128, (QKVW / 128) * (NTOK / 128), pos_sin, pos_cos);

    // s1: FF GEMM + gelu (needs ln) — overlaps QKV + attn
    cudaStreamWaitEvent(s1, eLN, 0);
    tgemm_kernel<<<PGRID, 128, DSMEM_BYTES, s1>>>(
        p_xn, HID, p_wt1 + (size_t)QKVW * HID, HID, b_in + QKVW, nullptr,
        p_comb + HID, COMBW, HID, 1, INTER / 128, (INTER / 128) * (NTOK / 128),
        nullptr, nullptr);
    cudaEventRecord(eF, s1);

    // s0: flash attention -> comb[:, :768]
    attn_kernel<<<dim3(NTOK / 128, NH), 256, ATTN_SMEM>>>(lenp);

    // join, then s0: out = xn + comb @ w_out + b_out
    cudaStreamWaitEvent(0, eF, 0);
    tgemm_kernel<<<PGRID, 128, DSMEM_BYTES>>>(
        p_comb, COMBW, p_wt2, COMBW, b_out, p_xn, out, HID,
        COMBW, 0, HID / 128, (HID / 128) * (NTOK / 128), nullptr, nullptr);
}

// round 14
// speedup vs baseline: 1.0528x; 1.0528x over previous
#include <cuda_runtime.h>
#include <cfloat>
#include <cstddef>
#include <cstdint>

#define HID   768
#define INTER 3072
#define NH    12
#define DH    64
#define NTOK  16384
#define WIN   256
#define CH    256
#define MIDW  (3*HID + INTER)   // 5376
#define QKVW  (3*HID)           // 2304
#define COMBW (HID + INTER)     // 3840

#define ASTR 36                       // gemm smem row stride in floats (pad 4)
#define TILE_BYTES (128 * ASTR * 4)   // 18432 per operand tile
#define STAGE_BYTES (2 * TILE_BYTES)  // A + B = 36864
#define GSTAGES 3
#define DSMEM_BYTES (GSTAGES * STAGE_BYTES) // 110592; 2 CTAs/SM = 216 KB

#define AQ   68                       // attn Q/K/V smem row stride (floats)
#define PSTR 36                       // attn probs smem row stride
#define ATTN_SMEM ((128*AQ + 32*AQ + 32*AQ) * 4)   // 52224 B

// Scratch (device globals: allocation inside kernel_launch is forbidden)
__device__ float g_xn  [(size_t)NTOK * HID];     //  50 MB
__device__ float g_comb[(size_t)NTOK * COMBW];   // 252 MB
__device__ float g_wt1 [(size_t)MIDW * HID];     //  16.5 MB
__device__ float g_wt2 [(size_t)HID * COMBW];    //  11.8 MB
__device__ float g_qr  [(size_t)NH * NTOK * DH]; //  50 MB  RoPE'd+scaled Q [h][tok][d]
__device__ float g_kr  [(size_t)NH * NTOK * DH]; //  50 MB  RoPE'd K
__device__ float g_vr  [(size_t)NH * NTOK * DH]; //  50 MB  V

// ---------------------------------------------------------------- helpers
__device__ __forceinline__ uint32_t smem_u32(const void* p) {
    uint32_t a;
    asm("{ .reg .u64 t; cvta.to.shared.u64 t, %1; cvt.u32.u64 %0, t; }"
        : "=r"(a) : "l"(p));
    return a;
}
__device__ __forceinline__ float f2tf32_rna(float x) {
    uint32_t u;
    asm("cvt.rna.tf32.f32 %0, %1;" : "=r"(u) : "f"(x));
    return __uint_as_float(u);
}
__device__ __forceinline__ void cp_async16(uint32_t dst, const void* src) {
    asm volatile("cp.async.cg.shared.global [%0], [%1], 16;"
                 :: "r"(dst), "l"(src) : "memory");
}
__device__ __forceinline__ void cp_commit() {
    asm volatile("cp.async.commit_group;" ::: "memory");
}
__device__ __forceinline__ void cp_wait1() {
    asm volatile("cp.async.wait_group 1;" ::: "memory");
}
__device__ __forceinline__ void cp_wait0() {
    asm volatile("cp.async.wait_group 0;" ::: "memory");
}
__device__ __forceinline__ uint32_t lds32(uint32_t addr) {
    uint32_t v;
    asm volatile("ld.shared.b32 %0, [%1];" : "=r"(v) : "r"(addr));
    return v;
}
__device__ __forceinline__ void mma_tf32(float* d, const uint32_t* a, const uint32_t* b) {
    asm volatile(
        "mma.sync.aligned.m16n8k8.row.col.f32.tf32.tf32.f32 "
        "{%0,%1,%2,%3}, {%4,%5,%6,%7}, {%8,%9}, {%0,%1,%2,%3};"
        : "+f"(d[0]), "+f"(d[1]), "+f"(d[2]), "+f"(d[3])
        : "r"(a[0]), "r"(a[1]), "r"(a[2]), "r"(a[3]), "r"(b[0]), "r"(b[1]));
}

// ---------------------------------------------------------------- GELU (tanh approx = jax default)
__device__ __forceinline__ float gelu_f(float x) {
    float x3 = x * x * x;
    return 0.5f * x * (1.0f + tanhf(0.7978845608028654f * (x + 0.044715f * x3)));
}

// ---------------------------------------------------------------- LayerNorm
__global__ void ln_kernel(const float* __restrict__ x,
                          const float* __restrict__ gam,
                          const float* __restrict__ bet)
{
    int row = blockIdx.x;
    int t   = threadIdx.x;
    const float* xr = x + (size_t)row * HID;
    float v0 = xr[t], v1 = xr[t + 256], v2 = xr[t + 512];
    float s  = v0 + v1 + v2;
    float s2 = v0*v0 + v1*v1 + v2*v2;
    #pragma unroll
    for (int o = 16; o > 0; o >>= 1) {
        s  += __shfl_xor_sync(0xffffffffu, s,  o);
        s2 += __shfl_xor_sync(0xffffffffu, s2, o);
    }
    __shared__ float red0[8], red1[8];
    __shared__ float stat[2];
    int w = t >> 5, l = t & 31;
    if (l == 0) { red0[w] = s; red1[w] = s2; }
    __syncthreads();
    if (t == 0) {
        float ts = 0.f, ts2 = 0.f;
        #pragma unroll
        for (int i = 0; i < 8; i++) { ts += red0[i]; ts2 += red1[i]; }
        float mu  = ts * (1.0f / HID);
        float var = ts2 * (1.0f / HID) - mu * mu;
        stat[0] = mu;
        stat[1] = rsqrtf(var + 1e-5f);
    }
    __syncthreads();
    float mu = stat[0], inv = stat[1];
    float* o = g_xn + (size_t)row * HID;
    o[t]       = (v0 - mu) * inv * gam[t]       + bet[t];
    o[t + 256] = (v1 - mu) * inv * gam[t + 256] + bet[t + 256];
    o[t + 512] = (v2 - mu) * inv * gam[t + 512] + bet[t + 512];
}

// ---------------------------------------------------------------- Transpose (R x C -> C x R), dims % 32 == 0
__global__ void transpose_kernel(const float* __restrict__ in, float* __restrict__ out,
                                 int R, int C)
{
    __shared__ float tile[32][33];
    int bx = blockIdx.x * 32, by = blockIdx.y * 32;
    int tx = threadIdx.x, ty = threadIdx.y;
    #pragma unroll
    for (int i = 0; i < 32; i += 8)
        tile[ty + i][tx] = in[(size_t)(by + ty + i) * C + bx + tx];
    __syncthreads();
    #pragma unroll
    for (int i = 0; i < 32; i += 8)
        out[(size_t)(bx + ty + i) * R + by + tx] = f2tf32_rna(tile[tx][ty + i]);
}

// ---------------------------------------------------------------- HMMA tf32 GEMM
// 128x128 CTA tile, 4 warps, 64x64 warp tile, 3-stage cp.async ring.
// One tile per CTA (R12 config — persistence regressed in R13).
// epi: 0 = bias (+R residual) -> C ; 1 = gelu(bias) -> C ;
//      2 = QKV mode: RoPE+scale -> g_qr/g_kr/g_vr (C unused)
__global__ __launch_bounds__(128, 2)
void tgemm_kernel(const float* __restrict__ A, int lda,
                  const float* __restrict__ Bt, int ldb,
                  const float* __restrict__ bias,
                  const float* __restrict__ R,
                  float* __restrict__ C, int ldc,
                  int K, int epi,
                  const float* __restrict__ psin,
                  const float* __restrict__ pcos)
{
    extern __shared__ float sm[];
    uint32_t sbase = smem_u32(sm);

    int t = threadIdx.x;
    int wid = t >> 5, lane = t & 31;
    int warp_m = (wid >> 1) * 64, warp_n = (wid & 1) * 64;
    int bm = blockIdx.y * 128, bn = blockIdx.x * 128;
    int r = lane >> 2, c = lane & 3;

    const float* Ag = A  + (size_t)bm * lda;
    const float* Bg = Bt + (size_t)bn * ldb;

    float acc[32][4];
    #pragma unroll
    for (int i = 0; i < 32; i++)
        #pragma unroll
        for (int j = 0; j < 4; j++) acc[i][j] = 0.f;

    int cm[8], ck[8];
    #pragma unroll
    for (int i = 0; i < 8; i++) {
        int id = t + i * 128;
        cm[i] = id >> 3;
        ck[i] = (id & 7) * 4;
    }

    auto load_stage = [&](int buf, int kbase) {
        uint32_t ab = sbase + (uint32_t)buf * STAGE_BYTES;
        uint32_t bb = ab + TILE_BYTES;
        #pragma unroll
        for (int i = 0; i < 8; i++) {
            cp_async16(ab + (uint32_t)(cm[i] * ASTR + ck[i]) * 4u,
                       Ag + (size_t)cm[i] * lda + kbase + ck[i]);
            cp_async16(bb + (uint32_t)(cm[i] * ASTR + ck[i]) * 4u,
                       Bg + (size_t)cm[i] * ldb + kbase + ck[i]);
        }
    };

    int S = K / 32;
    load_stage(0, 0);
    cp_commit();
    load_stage(1, 32);
    cp_commit();

    int buf = 0;
    for (int s = 0; s < S; s++) {
        if (s + 1 < S) cp_wait1();
        else           cp_wait0();
        __syncthreads();
        int nxt = s + 2;
        if (nxt < S) {
            int nbuf = buf + 2; if (nbuf >= GSTAGES) nbuf -= GSTAGES;
            load_stage(nbuf, nxt * 32);
            cp_commit();
        }

        uint32_t ab = sbase + (uint32_t)buf * STAGE_BYTES;
        uint32_t bb = ab + TILE_BYTES;
        #pragma unroll
        for (int ks = 0; ks < 4; ks++) {
            int k0 = ks * 8;
            uint32_t af[4][4];
            #pragma unroll
            for (int mt = 0; mt < 4; mt++) {
                uint32_t base = ab + (uint32_t)((warp_m + mt * 16 + r) * ASTR + k0 + c) * 4u;
                af[mt][0] = lds32(base);
                af[mt][1] = lds32(base + 8u * ASTR * 4u);
                af[mt][2] = lds32(base + 16u);
                af[mt][3] = lds32(base + 8u * ASTR * 4u + 16u);
            }
            uint32_t bf[8][2];
            #pragma unroll
            for (int nt = 0; nt < 8; nt++) {
                uint32_t base = bb + (uint32_t)((warp_n + nt * 8 + r) * ASTR + k0 + c) * 4u;
                bf[nt][0] = lds32(base);
                bf[nt][1] = lds32(base + 16u);
            }
            #pragma unroll
            for (int mt = 0; mt < 4; mt++)
                #pragma unroll
                for (int nt = 0; nt < 8; nt++)
                    mma_tf32(acc[mt * 8 + nt], af[mt], bf[nt]);
        }
        if (++buf == GSTAGES) buf = 0;
    }

    // ---- epilogue ----
    #pragma unroll
    for (int mt = 0; mt < 4; mt++) {
        #pragma unroll
        for (int nt = 0; nt < 8; nt++) {
            float* a4 = acc[mt * 8 + nt];
            int gm0 = bm + warp_m + mt * 16 + r;
            int gn  = bn + warp_n + nt * 8 + c * 2;
            float bx = bias[gn], by = bias[gn + 1];
            #pragma unroll
            for (int half = 0; half < 2; half++) {
                int gm = gm0 + half * 8;
                float vx = a4[half * 2 + 0] + bx;
                float vy = a4[half * 2 + 1] + by;
                if (epi == 2) {
                    // QKV: RoPE (+0.125 scale for q), tf32-round, scatter
                    int sec = gn / HID;            // 0=q 1=k 2=v
                    int rem = gn - sec * HID;
                    int h = rem >> 6, d = rem & 63;
                    size_t off = ((size_t)h * NTOK + gm) * DH + d;
                    if (sec == 2) {
                        *(float2*)(g_vr + off) =
                            make_float2(f2tf32_rna(vx), f2tf32_rna(vy));
                    } else {
                        float2 sv = *(const float2*)(psin + (size_t)gm * DH + d);
                        float2 cv = *(const float2*)(pcos + (size_t)gm * DH + d);
                        float ox = vx * cv.x - vy * sv.x;
                        float oy = vy * cv.y + vx * sv.y;
                        if (sec == 0) {
                            ox *= 0.125f; oy *= 0.125f;
                            *(float2*)(g_qr + off) =
                                make_float2(f2tf32_rna(ox), f2tf32_rna(oy));
                        } else {
                            *(float2*)(g_kr + off) =
                                make_float2(f2tf32_rna(ox), f2tf32_rna(oy));
                        }
                    }
                } else {
                    if (R) {
                        const float* rp = R + (size_t)gm * ldc + gn;
                        vx += rp[0]; vy += rp[1];
                    }
                    if (epi == 1) { vx = gelu_f(vx); vy = gelu_f(vy); }
                    *(float2*)(C + (size_t)gm * ldc + gn) = make_float2(vx, vy);
                }
            }
        }
    }
}

// ---------------------------------------------------------------- Attention (flash, mma.sync tf32; unchanged from R11)
__global__ __launch_bounds__(256, 2)
void attn_kernel(const int* __restrict__ lenp)
{
    extern __shared__ float sma[];
    float* Qs = sma;
    float* Ks = sma + 128 * AQ;
    float* Vs = Ks + 32 * AQ;
    float* Ps = Qs;

    int blk = blockIdx.x, h = blockIdx.y;
    int t = threadIdx.x, wid = t >> 5, lane = t & 31;
    int r = lane >> 2, cc = lane & 3;
    int q0  = blk * 128;
    int q0w = q0 + wid * 16;
    unsigned lm = ~((unsigned)(*lenp) - 1u);
    int qlo = q0w + r, qhi = qlo + 8;
    unsigned seqlo = (unsigned)qlo & lm, seqhi = (unsigned)qhi & lm;

    const float* Qg = g_qr + ((size_t)h * NTOK + q0) * DH;
    const float* Kg = g_kr + (size_t)h * NTOK * DH;
    const float* Vg = g_vr + (size_t)h * NTOK * DH;

    #pragma unroll
    for (int i = 0; i < 8; i++) {
        int f = t + i * 256;
        int row = f >> 4, c4 = f & 15;
        *(float4*)&Qs[row * AQ + c4 * 4] = *(const float4*)(Qg + (size_t)row * DH + c4 * 4);
    }
    __syncthreads();

    uint32_t qf[8][4];
    #pragma unroll
    for (int ks = 0; ks < 8; ks++) {
        const float* base = &Qs[(wid * 16 + r) * AQ + ks * 8 + cc];
        qf[ks][0] = __float_as_uint(base[0]);
        qf[ks][1] = __float_as_uint(base[8 * AQ]);
        qf[ks][2] = __float_as_uint(base[4]);
        qf[ks][3] = __float_as_uint(base[8 * AQ + 4]);
    }

    float o[8][4];
    #pragma unroll
    for (int i = 0; i < 8; i++)
        #pragma unroll
        for (int j = 0; j < 4; j++) o[i][j] = 0.f;
    float m_lo = -1e30f, m_hi = -1e30f, l_lo = 0.f, l_hi = 0.f;

    int kt0 = (q0 < 256) ? ((256 - q0) >> 5) : 0;

    for (int kt = kt0; kt < 12; kt++) {
        int kbase = q0 - 256 + kt * 32;
        __syncthreads();
        #pragma unroll
        for (int i = 0; i < 2; i++) {
            int f = t + i * 256;
            int row = f >> 4, c4 = f & 15;
            *(float4*)&Ks[row * AQ + c4 * 4] = *(const float4*)(Kg + (size_t)(kbase + row) * DH + c4 * 4);
            *(float4*)&Vs[row * AQ + c4 * 4] = *(const float4*)(Vg + (size_t)(kbase + row) * DH + c4 * 4);
        }
        __syncthreads();

        bool active = (kbase <= q0w + 15) && (q0w - (kbase + 31) < WIN);
        if (active) {
            float sc[4][4];
            #pragma unroll
            for (int nt = 0; nt < 4; nt++) {
                sc[nt][0] = sc[nt][1] = sc[nt][2] = sc[nt][3] = 0.f;
                #pragma unroll
                for (int ks = 0; ks < 8; ks++) {
                    const float* bb = &Ks[(nt * 8 + r) * AQ + ks * 8 + cc];
                    uint32_t bf[2] = { __float_as_uint(bb[0]), __float_as_uint(bb[4]) };
                    mma_tf32(sc[nt], qf[ks], bf);
                }
            }
            float tlo = -1e30f, thi = -1e30f;
            #pragma unroll
            for (int nt = 0; nt < 4; nt++) {
                #pragma unroll
                for (int b = 0; b < 2; b++) {
                    int ktok = kbase + nt * 8 + 2 * cc + b;
                    unsigned kseq = (unsigned)ktok & lm;
                    int dlo = qlo - ktok, dhi = qhi - ktok;
                    if (!(dlo >= 0 && dlo < WIN && kseq == seqlo)) sc[nt][b]     = -2e30f;
                    if (!(dhi >= 0 && dhi < WIN && kseq == seqhi)) sc[nt][2 + b] = -2e30f;
                    tlo = fmaxf(tlo, sc[nt][b]);
                    thi = fmaxf(thi, sc[nt][2 + b]);
                }
            }
            tlo = fmaxf(tlo, __shfl_xor_sync(0xffffffffu, tlo, 1));
            tlo = fmaxf(tlo, __shfl_xor_sync(0xffffffffu, tlo, 2));
            thi = fmaxf(thi, __shfl_xor_sync(0xffffffffu, thi, 1));
            thi = fmaxf(thi, __shfl_xor_sync(0xffffffffu, thi, 2));

            float mn_lo = fmaxf(m_lo, tlo), mn_hi = fmaxf(m_hi, thi);
            float co_lo = __expf(m_lo - mn_lo), co_hi = __expf(m_hi - mn_hi);
            m_lo = mn_lo; m_hi = mn_hi;
            l_lo *= co_lo; l_hi *= co_hi;
            #pragma unroll
            for (int i = 0; i < 8; i++) {
                o[i][0] *= co_lo; o[i][1] *= co_lo;
                o[i][2] *= co_hi; o[i][3] *= co_hi;
            }
            float* Pw = Ps + wid * 16 * PSTR;
            #pragma unroll
            for (int nt = 0; nt < 4; nt++) {
                float p0 = f2tf32_rna(__expf(sc[nt][0] - mn_lo));
                float p1 = f2tf32_rna(__expf(sc[nt][1] - mn_lo));
                float p2 = f2tf32_rna(__expf(sc[nt][2] - mn_hi));
                float p3 = f2tf32_rna(__expf(sc[nt][3] - mn_hi));
                l_lo += p0 + p1; l_hi += p2 + p3;
                Pw[r * PSTR + nt * 8 + 2 * cc]           = p0;
                Pw[r * PSTR + nt * 8 + 2 * cc + 1]       = p1;
                Pw[(r + 8) * PSTR + nt * 8 + 2 * cc]     = p2;
                Pw[(r + 8) * PSTR + nt * 8 + 2 * cc + 1] = p3;
            }
            __syncwarp();
            uint32_t pf[4][4];
            #pragma unroll
            for (int kk = 0; kk < 4; kk++) {
                const float* base = &Pw[r * PSTR + kk * 8 + cc];
                pf[kk][0] = __float_as_uint(base[0]);
                pf[kk][1] = __float_as_uint(base[8 * PSTR]);
                pf[kk][2] = __float_as_uint(base[4]);
                pf[kk][3] = __float_as_uint(base[8 * PSTR + 4]);
            }
            #pragma unroll
            for (int ntd = 0; ntd < 8; ntd++) {
                #pragma unroll
                for (int kk = 0; kk < 4; kk++) {
                    uint32_t bf[2] = {
                        __float_as_uint(Vs[(kk * 8 + cc) * AQ + ntd * 8 + r]),
                        __float_as_uint(Vs[(kk * 8 + cc + 4) * AQ + ntd * 8 + r]) };
                    mma_tf32(o[ntd], pf[kk], bf);
                }
            }
        }
    }

    l_lo += __shfl_xor_sync(0xffffffffu, l_lo, 1);
    l_lo += __shfl_xor_sync(0xffffffffu, l_lo, 2);
    l_hi += __shfl_xor_sync(0xffffffffu, l_hi, 1);
    l_hi += __shfl_xor_sync(0xffffffffu, l_hi, 2);
    float ilo = 1.0f / l_lo, ihi = 1.0f / l_hi;
    float* out_lo = g_comb + (size_t)qlo * COMBW + h * DH;
    float* out_hi = g_comb + (size_t)qhi * COMBW + h * DH;
    #pragma unroll
    for (int ntd = 0; ntd < 8; ntd++) {
        int gn = ntd * 8 + 2 * cc;
        *(float2*)(out_lo + gn) = make_float2(o[ntd][0] * ilo, o[ntd][1] * ilo);
        *(float2*)(out_hi + gn) = make_float2(o[ntd][2] * ihi, o[ntd][3] * ihi);
    }
}

// ---------------------------------------------------------------- launch
extern "C" void kernel_launch(void* const* d_in, const int* in_sizes, int n_in,
                              void* d_out, int out_size)
{
    (void)in_sizes; (void)n_in; (void)out_size;
    const float* x        = (const float*)d_in[0];
    const float* pos_sin  = (const float*)d_in[2];
    const float* pos_cos  = (const float*)d_in[3];
    const float* ln_scale = (const float*)d_in[4];
    const float* ln_off   = (const float*)d_in[5];
    const float* w_in     = (const float*)d_in[6];
    const float* b_in     = (const float*)d_in[7];
    const float* w_out    = (const float*)d_in[8];
    const float* b_out    = (const float*)d_in[9];
    const int*   lenp     = (const int*)d_in[10];
    float* out = (float*)d_out;

    static float *p_xn = nullptr, *p_comb = nullptr,
                 *p_wt1 = nullptr, *p_wt2 = nullptr;
    static cudaStream_t s1 = nullptr;
    static cudaEvent_t e0 = nullptr, eT = nullptr, eLN = nullptr, eF = nullptr;
    if (!p_xn) {
        cudaGetSymbolAddress((void**)&p_xn,   g_xn);
        cudaGetSymbolAddress((void**)&p_comb, g_comb);
        cudaGetSymbolAddress((void**)&p_wt1,  g_wt1);
        cudaGetSymbolAddress((void**)&p_wt2,  g_wt2);
        cudaFuncSetAttribute(tgemm_kernel,
                             cudaFuncAttributeMaxDynamicSharedMemorySize, DSMEM_BYTES);
        cudaFuncSetAttribute(attn_kernel,
                             cudaFuncAttributeMaxDynamicSharedMemorySize, ATTN_SMEM);
        cudaStreamCreateWithFlags(&s1, cudaStreamNonBlocking);
        cudaEventCreateWithFlags(&e0,  cudaEventDisableTiming);
        cudaEventCreateWithFlags(&eT,  cudaEventDisableTiming);
        cudaEventCreateWithFlags(&eLN, cudaEventDisableTiming);
        cudaEventCreateWithFlags(&eF,  cudaEventDisableTiming);
    }

    // fork s1 from the (captured) default stream
    cudaEventRecord(e0, 0);
    cudaStreamWaitEvent(s1, e0, 0);

    // s1: weight transposes (+tf32 round); s0: layernorm
    transpose_kernel<<<dim3(MIDW / 32, HID / 32),   dim3(32, 8), 0, s1>>>(w_in,  p_wt1, HID,   MIDW);
    transpose_kernel<<<dim3(HID / 32,  COMBW / 32), dim3(32, 8), 0, s1>>>(w_out, p_wt2, COMBW, HID);
    ln_kernel<<<NTOK, 256>>>(x, ln_scale, ln_off);
    cudaEventRecord(eLN, 0);

    // s0: QKV GEMM with fused RoPE epilogue -> g_qr/g_kr/g_vr (needs wt1)
    cudaEventRecord(eT, s1);
    cudaStreamWaitEvent(0, eT, 0);
    tgemm_kernel<<<dim3(QKVW / 128, NTOK / 128), 128, DSMEM_BYTES>>>(
        p_xn, HID, p_wt1, HID, b_in, nullptr, nullptr, 0,
        HID, 2, pos_sin, pos_cos);

    // s1: FF GEMM + gelu (needs ln) — overlaps QKV + attn
    cudaStreamWaitEvent(s1, eLN, 0);
    tgemm_kernel<<<dim3(INTER / 128, NTOK / 128), 128, DSMEM_BYTES, s1>>>(
        p_xn, HID, p_wt1 + (size_t)QKVW * HID, HID, b_in + QKVW, nullptr,
        p_comb + HID, COMBW, HID, 1, nullptr, nullptr);
    cudaEventRecord(eF, s1);

    // s0: flash attention -> comb[:, :768]
    attn_kernel<<<dim3(NTOK / 128, NH), 256, ATTN_SMEM>>>(lenp);

    // join, then s0: out = xn + comb @ w_out + b_out
    cudaStreamWaitEvent(0, eF, 0);
    tgemm_kernel<<<dim3(HID / 128, NTOK / 128), 128, DSMEM_BYTES>>>(
        p_comb, COMBW, p_wt2, COMBW, b_out, p_xn, out, HID,
        COMBW, 0, nullptr, nullptr);
}

// round 15
// speedup vs baseline: 1.7048x; 1.6193x over previous
#include <cuda_runtime.h>
#include <cuda_fp16.h>
#include <cfloat>
#include <cstddef>
#include <cstdint>

#define HID   768
#define INTER 3072
#define NH    12
#define DH    64
#define NTOK  16384
#define WIN   256
#define MIDW  (3*HID + INTER)   // 5376
#define QKVW  (3*HID)           // 2304
#define COMBW (HID + INTER)     // 3840

#define ASTRH 72                      // fp16 gemm smem row stride (halfs), 144B
#define TILE_BYTES (128 * ASTRH * 2)  // 18432 per operand tile (128 x 64 halfs + pad)
#define STAGE_BYTES (2 * TILE_BYTES)  // 36864
#define GSTAGES 3
#define DSMEM_BYTES (GSTAGES * STAGE_BYTES) // 110592; 2 CTAs/SM = 216 KB

#define AQ   68                       // attn Q/K/V smem row stride (floats)
#define PSTR 36                       // attn probs smem row stride
#define ATTN_SMEM ((128*AQ + 32*AQ + 32*AQ) * 4)   // 52224 B

// Scratch (device globals: allocation inside kernel_launch is forbidden)
__device__ float  g_xn  [(size_t)NTOK * HID];     // f32 xn (residual)
__device__ __half g_xnh [(size_t)NTOK * HID];     // fp16 xn (GEMM A)
__device__ __half g_combh[(size_t)NTOK * COMBW];  // fp16 [attn | gelu(ff)]
__device__ __half g_wt1h[(size_t)MIDW * HID];     // fp16 w_in^T
__device__ __half g_wt2h[(size_t)HID * COMBW];    // fp16 w_out^T
__device__ float  g_qr  [(size_t)NH * NTOK * DH]; // tf32-rounded RoPE'd Q (scaled)
__device__ float  g_kr  [(size_t)NH * NTOK * DH]; // tf32-rounded RoPE'd K
__device__ float  g_vr  [(size_t)NH * NTOK * DH]; // tf32-rounded V

// ---------------------------------------------------------------- helpers
__device__ __forceinline__ uint32_t smem_u32(const void* p) {
    uint32_t a;
    asm("{ .reg .u64 t; cvta.to.shared.u64 t, %1; cvt.u32.u64 %0, t; }"
        : "=r"(a) : "l"(p));
    return a;
}
__device__ __forceinline__ float f2tf32_rna(float x) {
    uint32_t u;
    asm("cvt.rna.tf32.f32 %0, %1;" : "=r"(u) : "f"(x));
    return __uint_as_float(u);
}
__device__ __forceinline__ void cp_async16(uint32_t dst, const void* src) {
    asm volatile("cp.async.cg.shared.global [%0], [%1], 16;"
                 :: "r"(dst), "l"(src) : "memory");
}
__device__ __forceinline__ void cp_commit() {
    asm volatile("cp.async.commit_group;" ::: "memory");
}
__device__ __forceinline__ void cp_wait1() {
    asm volatile("cp.async.wait_group 1;" ::: "memory");
}
__device__ __forceinline__ void cp_wait0() {
    asm volatile("cp.async.wait_group 0;" ::: "memory");
}
__device__ __forceinline__ uint32_t lds32(uint32_t addr) {
    uint32_t v;
    asm volatile("ld.shared.b32 %0, [%1];" : "=r"(v) : "r"(addr));
    return v;
}
// fp16 HMMA: D(f32) += A(f16) x B(f16), m16n8k16
__device__ __forceinline__ void mma_f16(float* d, const uint32_t* a, const uint32_t* b) {
    asm volatile(
        "mma.sync.aligned.m16n8k16.row.col.f32.f16.f16.f32 "
        "{%0,%1,%2,%3}, {%4,%5,%6,%7}, {%8,%9}, {%0,%1,%2,%3};"
        : "+f"(d[0]), "+f"(d[1]), "+f"(d[2]), "+f"(d[3])
        : "r"(a[0]), "r"(a[1]), "r"(a[2]), "r"(a[3]), "r"(b[0]), "r"(b[1]));
}
// tf32 HMMA (attention)
__device__ __forceinline__ void mma_tf32(float* d, const uint32_t* a, const uint32_t* b) {
    asm volatile(
        "mma.sync.aligned.m16n8k8.row.col.f32.tf32.tf32.f32 "
        "{%0,%1,%2,%3}, {%4,%5,%6,%7}, {%8,%9}, {%0,%1,%2,%3};"
        : "+f"(d[0]), "+f"(d[1]), "+f"(d[2]), "+f"(d[3])
        : "r"(a[0]), "r"(a[1]), "r"(a[2]), "r"(a[3]), "r"(b[0]), "r"(b[1]));
}

// ---------------------------------------------------------------- GELU (tanh approx = jax default)
__device__ __forceinline__ float gelu_f(float x) {
    float x3 = x * x * x;
    return 0.5f * x * (1.0f + tanhf(0.7978845608028654f * (x + 0.044715f * x3)));
}

// ---------------------------------------------------------------- LayerNorm (f32 + fp16 outputs)
__global__ void ln_kernel(const float* __restrict__ x,
                          const float* __restrict__ gam,
                          const float* __restrict__ bet)
{
    int row = blockIdx.x;
    int t   = threadIdx.x;
    const float* xr = x + (size_t)row * HID;
    float v0 = xr[t], v1 = xr[t + 256], v2 = xr[t + 512];
    float s  = v0 + v1 + v2;
    float s2 = v0*v0 + v1*v1 + v2*v2;
    #pragma unroll
    for (int o = 16; o > 0; o >>= 1) {
        s  += __shfl_xor_sync(0xffffffffu, s,  o);
        s2 += __shfl_xor_sync(0xffffffffu, s2, o);
    }
    __shared__ float red0[8], red1[8];
    __shared__ float stat[2];
    int w = t >> 5, l = t & 31;
    if (l == 0) { red0[w] = s; red1[w] = s2; }
    __syncthreads();
    if (t == 0) {
        float ts = 0.f, ts2 = 0.f;
        #pragma unroll
        for (int i = 0; i < 8; i++) { ts += red0[i]; ts2 += red1[i]; }
        float mu  = ts * (1.0f / HID);
        float var = ts2 * (1.0f / HID) - mu * mu;
        stat[0] = mu;
        stat[1] = rsqrtf(var + 1e-5f);
    }
    __syncthreads();
    float mu = stat[0], inv = stat[1];
    float* o  = g_xn  + (size_t)row * HID;
    __half* oh = g_xnh + (size_t)row * HID;
    float r0 = (v0 - mu) * inv * gam[t]       + bet[t];
    float r1 = (v1 - mu) * inv * gam[t + 256] + bet[t + 256];
    float r2 = (v2 - mu) * inv * gam[t + 512] + bet[t + 512];
    o[t] = r0;  o[t + 256] = r1;  o[t + 512] = r2;
    oh[t] = __float2half_rn(r0);
    oh[t + 256] = __float2half_rn(r1);
    oh[t + 512] = __float2half_rn(r2);
}

// ---------------------------------------------------------------- Transpose f32 -> fp16 (R x C -> C x R)
__global__ void transpose_kernel(const float* __restrict__ in, __half* __restrict__ out,
                                 int R, int C)
{
    __shared__ float tile[32][33];
    int bx = blockIdx.x * 32, by = blockIdx.y * 32;
    int tx = threadIdx.x, ty = threadIdx.y;
    #pragma unroll
    for (int i = 0; i < 32; i += 8)
        tile[ty + i][tx] = in[(size_t)(by + ty + i) * C + bx + tx];
    __syncthreads();
    #pragma unroll
    for (int i = 0; i < 32; i += 8)
        out[(size_t)(bx + ty + i) * R + by + tx] = __float2half_rn(tile[tx][ty + i]);
}

// ---------------------------------------------------------------- fp16 HMMA GEMM
// 128x128 CTA tile, 4 warps, 64x64 warp tile, 3-stage ring, K-stage = 64.
// epi: 0 = bias + R(f32) residual -> Cf(f32) ; 1 = gelu(bias) -> Ch(fp16) ;
//      2 = QKV: RoPE+scale, tf32-round -> g_qr/g_kr/g_vr
__global__ __launch_bounds__(128, 2)
void hgemm_kernel(const __half* __restrict__ A, int lda,
                  const __half* __restrict__ Bt, int ldb,
                  const float* __restrict__ bias,
                  const float* __restrict__ Rres,
                  float* __restrict__ Cf, __half* __restrict__ Ch, int ldc,
                  int K, int epi,
                  const float* __restrict__ psin,
                  const float* __restrict__ pcos)
{
    extern __shared__ __half smh[];
    uint32_t sbase = smem_u32(smh);

    int t = threadIdx.x;
    int wid = t >> 5, lane = t & 31;
    int warp_m = (wid >> 1) * 64, warp_n = (wid & 1) * 64;
    int bm = blockIdx.y * 128, bn = blockIdx.x * 128;
    int r = lane >> 2, c = lane & 3;

    const __half* Ag = A  + (size_t)bm * lda;
    const __half* Bg = Bt + (size_t)bn * ldb;

    float acc[32][4];
    #pragma unroll
    for (int i = 0; i < 32; i++)
        #pragma unroll
        for (int j = 0; j < 4; j++) acc[i][j] = 0.f;

    // 1024 16B-chunks per operand per stage (128 rows x 8 chunks), 8 per thread
    int cm[8], ck[8];
    #pragma unroll
    for (int i = 0; i < 8; i++) {
        int id = t + i * 128;
        cm[i] = id >> 3;              // row 0..127
        ck[i] = (id & 7) * 8;         // half offset within 64-half row
    }

    auto load_stage = [&](int buf, int kbase) {
        uint32_t ab = sbase + (uint32_t)buf * STAGE_BYTES;
        uint32_t bb = ab + TILE_BYTES;
        #pragma unroll
        for (int i = 0; i < 8; i++) {
            cp_async16(ab + (uint32_t)(cm[i] * ASTRH + ck[i]) * 2u,
                       Ag + (size_t)cm[i] * lda + kbase + ck[i]);
            cp_async16(bb + (uint32_t)(cm[i] * ASTRH + ck[i]) * 2u,
                       Bg + (size_t)cm[i] * ldb + kbase + ck[i]);
        }
    };

    int S = K / 64;   // K % 64 == 0 at all call sites (768, 3840)
    load_stage(0, 0);
    cp_commit();
    load_stage(1, 64);
    cp_commit();

    int buf = 0;
    for (int s = 0; s < S; s++) {
        if (s + 1 < S) cp_wait1();
        else           cp_wait0();
        __syncthreads();
        int nxt = s + 2;
        if (nxt < S) {
            int nbuf = buf + 2; if (nbuf >= GSTAGES) nbuf -= GSTAGES;
            load_stage(nbuf, nxt * 64);
            cp_commit();
        }

        uint32_t ab = sbase + (uint32_t)buf * STAGE_BYTES;
        uint32_t bb = ab + TILE_BYTES;
        #pragma unroll
        for (int ks = 0; ks < 4; ks++) {
            int k0 = ks * 16;
            uint32_t af[4][4];
            #pragma unroll
            for (int mt = 0; mt < 4; mt++) {
                uint32_t base = ab + (uint32_t)((warp_m + mt * 16 + r) * ASTRH + k0 + 2 * c) * 2u;
                af[mt][0] = lds32(base);                       // (r,   k0+2c..+1)
                af[mt][1] = lds32(base + 8u * ASTRH * 2u);     // (r+8, k0+2c..+1)
                af[mt][2] = lds32(base + 16u);                 // (r,   k0+8+2c..+1)
                af[mt][3] = lds32(base + 8u * ASTRH * 2u + 16u);
            }
            uint32_t bf[8][2];
            #pragma unroll
            for (int nt = 0; nt < 8; nt++) {
                uint32_t base = bb + (uint32_t)((warp_n + nt * 8 + r) * ASTRH + k0 + 2 * c) * 2u;
                bf[nt][0] = lds32(base);                       // (n=r, k0+2c..+1)
                bf[nt][1] = lds32(base + 16u);                 // (n=r, k0+8+2c..+1)
            }
            #pragma unroll
            for (int mt = 0; mt < 4; mt++)
                #pragma unroll
                for (int nt = 0; nt < 8; nt++)
                    mma_f16(acc[mt * 8 + nt], af[mt], bf[nt]);
        }
        if (++buf == GSTAGES) buf = 0;
    }

    // ---- epilogue (C frag map: c0:(r,2c) c1:(r,2c+1) c2:(r+8,2c) c3:(r+8,2c+1))
    #pragma unroll
    for (int mt = 0; mt < 4; mt++) {
        #pragma unroll
        for (int nt = 0; nt < 8; nt++) {
            float* a4 = acc[mt * 8 + nt];
            int gm0 = bm + warp_m + mt * 16 + r;
            int gn  = bn + warp_n + nt * 8 + c * 2;
            float bx = bias[gn], by = bias[gn + 1];
            #pragma unroll
            for (int half = 0; half < 2; half++) {
                int gm = gm0 + half * 8;
                float vx = a4[half * 2 + 0] + bx;
                float vy = a4[half * 2 + 1] + by;
                if (epi == 2) {
                    int sec = gn / HID;            // 0=q 1=k 2=v
                    int rem = gn - sec * HID;
                    int h = rem >> 6, d = rem & 63;
                    size_t off = ((size_t)h * NTOK + gm) * DH + d;
                    if (sec == 2) {
                        *(float2*)(g_vr + off) =
                            make_float2(f2tf32_rna(vx), f2tf32_rna(vy));
                    } else {
                        float2 sv = *(const float2*)(psin + (size_t)gm * DH + d);
                        float2 cv = *(const float2*)(pcos + (size_t)gm * DH + d);
                        float ox = vx * cv.x - vy * sv.x;
                        float oy = vy * cv.y + vx * sv.y;
                        if (sec == 0) {
                            ox *= 0.125f; oy *= 0.125f;
                            *(float2*)(g_qr + off) =
                                make_float2(f2tf32_rna(ox), f2tf32_rna(oy));
                        } else {
                            *(float2*)(g_kr + off) =
                                make_float2(f2tf32_rna(ox), f2tf32_rna(oy));
                        }
                    }
                } else if (epi == 1) {
                    vx = gelu_f(vx); vy = gelu_f(vy);
                    *(__half2*)(Ch + (size_t)gm * ldc + gn) =
                        __floats2half2_rn(vx, vy);
                } else {
                    const float* rp = Rres + (size_t)gm * HID + gn;
                    vx += rp[0]; vy += rp[1];
                    *(float2*)(Cf + (size_t)gm * ldc + gn) = make_float2(vx, vy);
                }
            }
        }
    }
}

// ---------------------------------------------------------------- Attention (flash, mma.sync tf32)
__global__ __launch_bounds__(256, 2)
void attn_kernel(const int* __restrict__ lenp)
{
    extern __shared__ float sma[];
    float* Qs = sma;
    float* Ks = sma + 128 * AQ;
    float* Vs = Ks + 32 * AQ;
    float* Ps = Qs;

    int blk = blockIdx.x, h = blockIdx.y;
    int t = threadIdx.x, wid = t >> 5, lane = t & 31;
    int r = lane >> 2, cc = lane & 3;
    int q0  = blk * 128;
    int q0w = q0 + wid * 16;
    unsigned lm = ~((unsigned)(*lenp) - 1u);
    int qlo = q0w + r, qhi = qlo + 8;
    unsigned seqlo = (unsigned)qlo & lm, seqhi = (unsigned)qhi & lm;

    const float* Qg = g_qr + ((size_t)h * NTOK + q0) * DH;
    const float* Kg = g_kr + (size_t)h * NTOK * DH;
    const float* Vg = g_vr + (size_t)h * NTOK * DH;

    #pragma unroll
    for (int i = 0; i < 8; i++) {
        int f = t + i * 256;
        int row = f >> 4, c4 = f & 15;
        *(float4*)&Qs[row * AQ + c4 * 4] = *(const float4*)(Qg + (size_t)row * DH + c4 * 4);
    }
    __syncthreads();

    uint32_t qf[8][4];
    #pragma unroll
    for (int ks = 0; ks < 8; ks++) {
        const float* base = &Qs[(wid * 16 + r) * AQ + ks * 8 + cc];
        qf[ks][0] = __float_as_uint(base[0]);
        qf[ks][1] = __float_as_uint(base[8 * AQ]);
        qf[ks][2] = __float_as_uint(base[4]);
        qf[ks][3] = __float_as_uint(base[8 * AQ + 4]);
    }

    float o[8][4];
    #pragma unroll
    for (int i = 0; i < 8; i++)
        #pragma unroll
        for (int j = 0; j < 4; j++) o[i][j] = 0.f;
    float m_lo = -1e30f, m_hi = -1e30f, l_lo = 0.f, l_hi = 0.f;

    int kt0 = (q0 < 256) ? ((256 - q0) >> 5) : 0;

    for (int kt = kt0; kt < 12; kt++) {
        int kbase = q0 - 256 + kt * 32;
        __syncthreads();
        #pragma unroll
        for (int i = 0; i < 2; i++) {
            int f = t + i * 256;
            int row = f >> 4, c4 = f & 15;
            *(float4*)&Ks[row * AQ + c4 * 4] = *(const float4*)(Kg + (size_t)(kbase + row) * DH + c4 * 4);
            *(float4*)&Vs[row * AQ + c4 * 4] = *(const float4*)(Vg + (size_t)(kbase + row) * DH + c4 * 4);
        }
        __syncthreads();

        bool active = (kbase <= q0w + 15) && (q0w - (kbase + 31) < WIN);
        if (active) {
            float sc[4][4];
            #pragma unroll
            for (int nt = 0; nt < 4; nt++) {
                sc[nt][0] = sc[nt][1] = sc[nt][2] = sc[nt][3] = 0.f;
                #pragma unroll
                for (int ks = 0; ks < 8; ks++) {
                    const float* bb = &Ks[(nt * 8 + r) * AQ + ks * 8 + cc];
                    uint32_t bf[2] = { __float_as_uint(bb[0]), __float_as_uint(bb[4]) };
                    mma_tf32(sc[nt], qf[ks], bf);
                }
            }
            float tlo = -1e30f, thi = -1e30f;
            #pragma unroll
            for (int nt = 0; nt < 4; nt++) {
                #pragma unroll
                for (int b = 0; b < 2; b++) {
                    int ktok = kbase + nt * 8 + 2 * cc + b;
                    unsigned kseq = (unsigned)ktok & lm;
                    int dlo = qlo - ktok, dhi = qhi - ktok;
                    if (!(dlo >= 0 && dlo < WIN && kseq == seqlo)) sc[nt][b]     = -2e30f;
                    if (!(dhi >= 0 && dhi < WIN && kseq == seqhi)) sc[nt][2 + b] = -2e30f;
                    tlo = fmaxf(tlo, sc[nt][b]);
                    thi = fmaxf(thi, sc[nt][2 + b]);
                }
            }
            tlo = fmaxf(tlo, __shfl_xor_sync(0xffffffffu, tlo, 1));
            tlo = fmaxf(tlo, __shfl_xor_sync(0xffffffffu, tlo, 2));
            thi = fmaxf(thi, __shfl_xor_sync(0xffffffffu, thi, 1));
            thi = fmaxf(thi, __shfl_xor_sync(0xffffffffu, thi, 2));

            float mn_lo = fmaxf(m_lo, tlo), mn_hi = fmaxf(m_hi, thi);
            float co_lo = __expf(m_lo - mn_lo), co_hi = __expf(m_hi - mn_hi);
            m_lo = mn_lo; m_hi = mn_hi;
            l_lo *= co_lo; l_hi *= co_hi;
            #pragma unroll
            for (int i = 0; i < 8; i++) {
                o[i][0] *= co_lo; o[i][1] *= co_lo;
                o[i][2] *= co_hi; o[i][3] *= co_hi;
            }
            float* Pw = Ps + wid * 16 * PSTR;
            #pragma unroll
            for (int nt = 0; nt < 4; nt++) {
                float p0 = f2tf32_rna(__expf(sc[nt][0] - mn_lo));
                float p1 = f2tf32_rna(__expf(sc[nt][1] - mn_lo));
                float p2 = f2tf32_rna(__expf(sc[nt][2] - mn_hi));
                float p3 = f2tf32_rna(__expf(sc[nt][3] - mn_hi));
                l_lo += p0 + p1; l_hi += p2 + p3;
                Pw[r * PSTR + nt * 8 + 2 * cc]           = p0;
                Pw[r * PSTR + nt * 8 + 2 * cc + 1]       = p1;
                Pw[(r + 8) * PSTR + nt * 8 + 2 * cc]     = p2;
                Pw[(r + 8) * PSTR + nt * 8 + 2 * cc + 1] = p3;
            }
            __syncwarp();
            uint32_t pf[4][4];
            #pragma unroll
            for (int kk = 0; kk < 4; kk++) {
                const float* base = &Pw[r * PSTR + kk * 8 + cc];
                pf[kk][0] = __float_as_uint(base[0]);
                pf[kk][1] = __float_as_uint(base[8 * PSTR]);
                pf[kk][2] = __float_as_uint(base[4]);
                pf[kk][3] = __float_as_uint(base[8 * PSTR + 4]);
            }
            #pragma unroll
            for (int ntd = 0; ntd < 8; ntd++) {
                #pragma unroll
                for (int kk = 0; kk < 4; kk++) {
                    uint32_t bf[2] = {
                        __float_as_uint(Vs[(kk * 8 + cc) * AQ + ntd * 8 + r]),
                        __float_as_uint(Vs[(kk * 8 + cc + 4) * AQ + ntd * 8 + r]) };
                    mma_tf32(o[ntd], pf[kk], bf);
                }
            }
        }
    }

    l_lo += __shfl_xor_sync(0xffffffffu, l_lo, 1);
    l_lo += __shfl_xor_sync(0xffffffffu, l_lo, 2);
    l_hi += __shfl_xor_sync(0xffffffffu, l_hi, 1);
    l_hi += __shfl_xor_sync(0xffffffffu, l_hi, 2);
    float ilo = 1.0f / l_lo, ihi = 1.0f / l_hi;
    __half* out_lo = g_combh + (size_t)qlo * COMBW + h * DH;
    __half* out_hi = g_combh + (size_t)qhi * COMBW + h * DH;
    #pragma unroll
    for (int ntd = 0; ntd < 8; ntd++) {
        int gn = ntd * 8 + 2 * cc;
        *(__half2*)(out_lo + gn) = __floats2half2_rn(o[ntd][0] * ilo, o[ntd][1] * ilo);
        *(__half2*)(out_hi + gn) = __floats2half2_rn(o[ntd][2] * ihi, o[ntd][3] * ihi);
    }
}

// ---------------------------------------------------------------- launch
extern "C" void kernel_launch(void* const* d_in, const int* in_sizes, int n_in,
                              void* d_out, int out_size)
{
    (void)in_sizes; (void)n_in; (void)out_size;
    const float* x        = (const float*)d_in[0];
    const float* pos_sin  = (const float*)d_in[2];
    const float* pos_cos  = (const float*)d_in[3];
    const float* ln_scale = (const float*)d_in[4];
    const float* ln_off   = (const float*)d_in[5];
    const float* w_in     = (const float*)d_in[6];
    const float* b_in     = (const float*)d_in[7];
    const float* w_out    = (const float*)d_in[8];
    const float* b_out    = (const float*)d_in[9];
    const int*   lenp     = (const int*)d_in[10];
    float* out = (float*)d_out;

    static float  *p_xn = nullptr;
    static __half *p_xnh = nullptr, *p_combh = nullptr, *p_wt1h = nullptr, *p_wt2h = nullptr;
    static cudaStream_t s1 = nullptr;
    static cudaEvent_t e0 = nullptr, eT = nullptr, eLN = nullptr, eF = nullptr;
    if (!p_xn) {
        cudaGetSymbolAddress((void**)&p_xn,    g_xn);
        cudaGetSymbolAddress((void**)&p_xnh,   g_xnh);
        cudaGetSymbolAddress((void**)&p_combh, g_combh);
        cudaGetSymbolAddress((void**)&p_wt1h,  g_wt1h);
        cudaGetSymbolAddress((void**)&p_wt2h,  g_wt2h);
        cudaFuncSetAttribute(hgemm_kernel,
                             cudaFuncAttributeMaxDynamicSharedMemorySize, DSMEM_BYTES);
        cudaFuncSetAttribute(attn_kernel,
                             cudaFuncAttributeMaxDynamicSharedMemorySize, ATTN_SMEM);
        cudaStreamCreateWithFlags(&s1, cudaStreamNonBlocking);
        cudaEventCreateWithFlags(&e0,  cudaEventDisableTiming);
        cudaEventCreateWithFlags(&eT,  cudaEventDisableTiming);
        cudaEventCreateWithFlags(&eLN, cudaEventDisableTiming);
        cudaEventCreateWithFlags(&eF,  cudaEventDisableTiming);
    }

    // fork s1 from the (captured) default stream
    cudaEventRecord(e0, 0);
    cudaStreamWaitEvent(s1, e0, 0);

    // s1: weight transposes (f32 -> fp16); s0: layernorm (f32 + fp16)
    transpose_kernel<<<dim3(MIDW / 32, HID / 32),   dim3(32, 8), 0, s1>>>(w_in,  p_wt1h, HID,   MIDW);
    transpose_kernel<<<dim3(HID / 32,  COMBW / 32), dim3(32, 8), 0, s1>>>(w_out, p_wt2h, COMBW, HID);
    ln_kernel<<<NTOK, 256>>>(x, ln_scale, ln_off);
    cudaEventRecord(eLN, 0);

    // s0: QKV GEMM + fused RoPE -> g_qr/g_kr/g_vr (needs wt1h)
    cudaEventRecord(eT, s1);
    cudaStreamWaitEvent(0, eT, 0);
    hgemm_kernel<<<dim3(QKVW / 128, NTOK / 128), 128, DSMEM_BYTES>>>(
        p_xnh, HID, p_wt1h, HID, b_in, nullptr, nullptr, nullptr, 0,
        HID, 2, pos_sin, pos_cos);

    // s1: FF GEMM + gelu -> combh[:, 768:] (needs ln) — overlaps QKV + attn
    cudaStreamWaitEvent(s1, eLN, 0);
    hgemm_kernel<<<dim3(INTER / 128, NTOK / 128), 128, DSMEM_BYTES, s1>>>(
        p_xnh, HID, p_wt1h + (size_t)QKVW * HID, HID, b_in + QKVW, nullptr,
        nullptr, p_combh + HID, COMBW, HID, 1, nullptr, nullptr);
    cudaEventRecord(eF, s1);

    // s0: flash attention -> combh[:, :768]
    attn_kernel<<<dim3(NTOK / 128, NH), 256, ATTN_SMEM>>>(lenp);

    // join, then s0: out = xn + combh @ w_out + b_out  (f32 residual/output)
    cudaStreamWaitEvent(0, eF, 0);
    hgemm_kernel<<<dim3(HID / 128, NTOK / 128), 128, DSMEM_BYTES>>>(
        p_combh, COMBW, p_wt2h, COMBW, b_out, p_xn, out, nullptr, HID,
        COMBW, 0, nullptr, nullptr);
}

// round 16
// speedup vs baseline: 1.7367x; 1.0187x over previous
#include <cuda_runtime.h>
#include <cuda_fp16.h>
#include <cfloat>
#include <cstddef>
#include <cstdint>

#define HID   768
#define INTER 3072
#define NH    12
#define DH    64
#define NTOK  16384
#define WIN   256
#define MIDW  (3*HID + INTER)   // 5376
#define QKVW  (3*HID)           // 2304
#define COMBW (HID + INTER)     // 3840

#define ASTRH 72                      // fp16 gemm smem row stride (halfs), 144B
#define TILE_BYTES (128 * ASTRH * 2)  // 18432 per operand tile (128 x 64 halfs + pad)
#define STAGE_BYTES (2 * TILE_BYTES)  // 36864
#define GSTAGES 3
#define DSMEM_BYTES (GSTAGES * STAGE_BYTES) // 110592; 2 CTAs/SM = 216 KB

#define AQ   68                       // attn Q/K/V smem row stride (floats)
#define PSTR 36                       // attn probs smem row stride
#define ATTN_SMEM ((128*AQ + 32*AQ + 32*AQ) * 4)   // 52224 B

// Scratch (device globals: allocation inside kernel_launch is forbidden)
__device__ float  g_xn  [(size_t)NTOK * HID];     // f32 xn (residual)
__device__ __half g_xnh [(size_t)NTOK * HID];     // fp16 xn (GEMM A)
__device__ __half g_combh[(size_t)NTOK * COMBW];  // fp16 [attn | gelu(ff)]
__device__ __half g_wt1h[(size_t)MIDW * HID];     // fp16 w_in^T
__device__ __half g_wt2h[(size_t)HID * COMBW];    // fp16 w_out^T
__device__ float  g_qr  [(size_t)NH * NTOK * DH]; // tf32-rounded RoPE'd Q (scaled)
__device__ float  g_kr  [(size_t)NH * NTOK * DH]; // tf32-rounded RoPE'd K
__device__ float  g_vr  [(size_t)NH * NTOK * DH]; // tf32-rounded V

// ---------------------------------------------------------------- helpers
__device__ __forceinline__ uint32_t smem_u32(const void* p) {
    uint32_t a;
    asm("{ .reg .u64 t; cvta.to.shared.u64 t, %1; cvt.u32.u64 %0, t; }"
        : "=r"(a) : "l"(p));
    return a;
}
__device__ __forceinline__ float f2tf32_rna(float x) {
    uint32_t u;
    asm("cvt.rna.tf32.f32 %0, %1;" : "=r"(u) : "f"(x));
    return __uint_as_float(u);
}
__device__ __forceinline__ void cp_async16(uint32_t dst, const void* src) {
    asm volatile("cp.async.cg.shared.global [%0], [%1], 16;"
                 :: "r"(dst), "l"(src) : "memory");
}
__device__ __forceinline__ void cp_commit() {
    asm volatile("cp.async.commit_group;" ::: "memory");
}
__device__ __forceinline__ void cp_wait1() {
    asm volatile("cp.async.wait_group 1;" ::: "memory");
}
__device__ __forceinline__ void cp_wait0() {
    asm volatile("cp.async.wait_group 0;" ::: "memory");
}
__device__ __forceinline__ uint32_t lds32(uint32_t addr) {
    uint32_t v;
    asm volatile("ld.shared.b32 %0, [%1];" : "=r"(v) : "r"(addr));
    return v;
}
// fp16 HMMA: D(f32) += A(f16) x B(f16), m16n8k16
__device__ __forceinline__ void mma_f16(float* d, const uint32_t* a, const uint32_t* b) {
    asm volatile(
        "mma.sync.aligned.m16n8k16.row.col.f32.f16.f16.f32 "
        "{%0,%1,%2,%3}, {%4,%5,%6,%7}, {%8,%9}, {%0,%1,%2,%3};"
        : "+f"(d[0]), "+f"(d[1]), "+f"(d[2]), "+f"(d[3])
        : "r"(a[0]), "r"(a[1]), "r"(a[2]), "r"(a[3]), "r"(b[0]), "r"(b[1]));
}
// tf32 HMMA (attention)
__device__ __forceinline__ void mma_tf32(float* d, const uint32_t* a, const uint32_t* b) {
    asm volatile(
        "mma.sync.aligned.m16n8k8.row.col.f32.tf32.tf32.f32 "
        "{%0,%1,%2,%3}, {%4,%5,%6,%7}, {%8,%9}, {%0,%1,%2,%3};"
        : "+f"(d[0]), "+f"(d[1]), "+f"(d[2]), "+f"(d[3])
        : "r"(a[0]), "r"(a[1]), "r"(a[2]), "r"(a[3]), "r"(b[0]), "r"(b[1]));
}

// ---------------------------------------------------------------- GELU (tanh approx = jax default)
__device__ __forceinline__ float gelu_f(float x) {
    float x3 = x * x * x;
    return 0.5f * x * (1.0f + tanhf(0.7978845608028654f * (x + 0.044715f * x3)));
}

// ---------------------------------------------------------------- LayerNorm (f32 + fp16 outputs)
__global__ void ln_kernel(const float* __restrict__ x,
                          const float* __restrict__ gam,
                          const float* __restrict__ bet)
{
    int row = blockIdx.x;
    int t   = threadIdx.x;
    const float* xr = x + (size_t)row * HID;
    float v0 = xr[t], v1 = xr[t + 256], v2 = xr[t + 512];
    float s  = v0 + v1 + v2;
    float s2 = v0*v0 + v1*v1 + v2*v2;
    #pragma unroll
    for (int o = 16; o > 0; o >>= 1) {
        s  += __shfl_xor_sync(0xffffffffu, s,  o);
        s2 += __shfl_xor_sync(0xffffffffu, s2, o);
    }
    __shared__ float red0[8], red1[8];
    __shared__ float stat[2];
    int w = t >> 5, l = t & 31;
    if (l == 0) { red0[w] = s; red1[w] = s2; }
    __syncthreads();
    if (t == 0) {
        float ts = 0.f, ts2 = 0.f;
        #pragma unroll
        for (int i = 0; i < 8; i++) { ts += red0[i]; ts2 += red1[i]; }
        float mu  = ts * (1.0f / HID);
        float var = ts2 * (1.0f / HID) - mu * mu;
        stat[0] = mu;
        stat[1] = rsqrtf(var + 1e-5f);
    }
    __syncthreads();
    float mu = stat[0], inv = stat[1];
    float* o  = g_xn  + (size_t)row * HID;
    __half* oh = g_xnh + (size_t)row * HID;
    float r0 = (v0 - mu) * inv * gam[t]       + bet[t];
    float r1 = (v1 - mu) * inv * gam[t + 256] + bet[t + 256];
    float r2 = (v2 - mu) * inv * gam[t + 512] + bet[t + 512];
    o[t] = r0;  o[t + 256] = r1;  o[t + 512] = r2;
    oh[t] = __float2half_rn(r0);
    oh[t + 256] = __float2half_rn(r1);
    oh[t + 512] = __float2half_rn(r2);
}

// ---------------------------------------------------------------- Transpose f32 -> fp16 (R x C -> C x R)
__global__ void transpose_kernel(const float* __restrict__ in, __half* __restrict__ out,
                                 int R, int C)
{
    __shared__ float tile[32][33];
    int bx = blockIdx.x * 32, by = blockIdx.y * 32;
    int tx = threadIdx.x, ty = threadIdx.y;
    #pragma unroll
    for (int i = 0; i < 32; i += 8)
        tile[ty + i][tx] = in[(size_t)(by + ty + i) * C + bx + tx];
    __syncthreads();
    #pragma unroll
    for (int i = 0; i < 32; i += 8)
        out[(size_t)(bx + ty + i) * R + by + tx] = __float2half_rn(tile[tx][ty + i]);
}

// ---------------------------------------------------------------- fp16 HMMA GEMM
// 128x128 CTA tile, 8 warps (256 thr), 64x32 warp tile (2x4 warp grid),
// 3-stage cp.async ring, K-stage = 64. 16 warps/SM for latency hiding.
// epi: 0 = bias + R(f32) residual -> Cf(f32) ; 1 = gelu(bias) -> Ch(fp16) ;
//      2 = QKV: RoPE+scale, tf32-round -> g_qr/g_kr/g_vr
__global__ __launch_bounds__(256, 2)
void hgemm_kernel(const __half* __restrict__ A, int lda,
                  const __half* __restrict__ Bt, int ldb,
                  const float* __restrict__ bias,
                  const float* __restrict__ Rres,
                  float* __restrict__ Cf, __half* __restrict__ Ch, int ldc,
                  int K, int epi,
                  const float* __restrict__ psin,
                  const float* __restrict__ pcos)
{
    extern __shared__ __half smh[];
    uint32_t sbase = smem_u32(smh);

    int t = threadIdx.x;
    int wid = t >> 5, lane = t & 31;
    int warp_m = (wid >> 2) * 64, warp_n = (wid & 3) * 32;
    int bm = blockIdx.y * 128, bn = blockIdx.x * 128;
    int r = lane >> 2, c = lane & 3;

    const __half* Ag = A  + (size_t)bm * lda;
    const __half* Bg = Bt + (size_t)bn * ldb;

    float acc[16][4];
    #pragma unroll
    for (int i = 0; i < 16; i++)
        #pragma unroll
        for (int j = 0; j < 4; j++) acc[i][j] = 0.f;

    // 1024 16B-chunks per operand per stage, 256 threads -> 4 each
    int cm[4], ck[4];
    #pragma unroll
    for (int i = 0; i < 4; i++) {
        int id = t + i * 256;
        cm[i] = id >> 3;              // row 0..127
        ck[i] = (id & 7) * 8;         // half offset within 64-half row
    }

    auto load_stage = [&](int buf, int kbase) {
        uint32_t ab = sbase + (uint32_t)buf * STAGE_BYTES;
        uint32_t bb = ab + TILE_BYTES;
        #pragma unroll
        for (int i = 0; i < 4; i++) {
            cp_async16(ab + (uint32_t)(cm[i] * ASTRH + ck[i]) * 2u,
                       Ag + (size_t)cm[i] * lda + kbase + ck[i]);
            cp_async16(bb + (uint32_t)(cm[i] * ASTRH + ck[i]) * 2u,
                       Bg + (size_t)cm[i] * ldb + kbase + ck[i]);
        }
    };

    int S = K / 64;   // K % 64 == 0 at all call sites (768, 3840)
    load_stage(0, 0);
    cp_commit();
    load_stage(1, 64);
    cp_commit();

    int buf = 0;
    for (int s = 0; s < S; s++) {
        if (s + 1 < S) cp_wait1();
        else           cp_wait0();
        __syncthreads();
        int nxt = s + 2;
        if (nxt < S) {
            int nbuf = buf + 2; if (nbuf >= GSTAGES) nbuf -= GSTAGES;
            load_stage(nbuf, nxt * 64);
            cp_commit();
        }

        uint32_t ab = sbase + (uint32_t)buf * STAGE_BYTES;
        uint32_t bb = ab + TILE_BYTES;
        #pragma unroll
        for (int ks = 0; ks < 4; ks++) {
            int k0 = ks * 16;
            uint32_t af[4][4];
            #pragma unroll
            for (int mt = 0; mt < 4; mt++) {
                uint32_t base = ab + (uint32_t)((warp_m + mt * 16 + r) * ASTRH + k0 + 2 * c) * 2u;
                af[mt][0] = lds32(base);
                af[mt][1] = lds32(base + 8u * ASTRH * 2u);
                af[mt][2] = lds32(base + 16u);
                af[mt][3] = lds32(base + 8u * ASTRH * 2u + 16u);
            }
            uint32_t bf[4][2];
            #pragma unroll
            for (int nt = 0; nt < 4; nt++) {
                uint32_t base = bb + (uint32_t)((warp_n + nt * 8 + r) * ASTRH + k0 + 2 * c) * 2u;
                bf[nt][0] = lds32(base);
                bf[nt][1] = lds32(base + 16u);
            }
            #pragma unroll
            for (int mt = 0; mt < 4; mt++)
                #pragma unroll
                for (int nt = 0; nt < 4; nt++)
                    mma_f16(acc[mt * 4 + nt], af[mt], bf[nt]);
        }
        if (++buf == GSTAGES) buf = 0;
    }

    // ---- epilogue (C frag map: c0:(r,2c) c1:(r,2c+1) c2:(r+8,2c) c3:(r+8,2c+1))
    #pragma unroll
    for (int mt = 0; mt < 4; mt++) {
        #pragma unroll
        for (int nt = 0; nt < 4; nt++) {
            float* a4 = acc[mt * 4 + nt];
            int gm0 = bm + warp_m + mt * 16 + r;
            int gn  = bn + warp_n + nt * 8 + c * 2;
            float bx = bias[gn], by = bias[gn + 1];
            #pragma unroll
            for (int half = 0; half < 2; half++) {
                int gm = gm0 + half * 8;
                float vx = a4[half * 2 + 0] + bx;
                float vy = a4[half * 2 + 1] + by;
                if (epi == 2) {
                    int sec = gn / HID;            // 0=q 1=k 2=v
                    int rem = gn - sec * HID;
                    int h = rem >> 6, d = rem & 63;
                    size_t off = ((size_t)h * NTOK + gm) * DH + d;
                    if (sec == 2) {
                        *(float2*)(g_vr + off) =
                            make_float2(f2tf32_rna(vx), f2tf32_rna(vy));
                    } else {
                        float2 sv = *(const float2*)(psin + (size_t)gm * DH + d);
                        float2 cv = *(const float2*)(pcos + (size_t)gm * DH + d);
                        float ox = vx * cv.x - vy * sv.x;
                        float oy = vy * cv.y + vx * sv.y;
                        if (sec == 0) {
                            ox *= 0.125f; oy *= 0.125f;
                            *(float2*)(g_qr + off) =
                                make_float2(f2tf32_rna(ox), f2tf32_rna(oy));
                        } else {
                            *(float2*)(g_kr + off) =
                                make_float2(f2tf32_rna(ox), f2tf32_rna(oy));
                        }
                    }
                } else if (epi == 1) {
                    vx = gelu_f(vx); vy = gelu_f(vy);
                    *(__half2*)(Ch + (size_t)gm * ldc + gn) =
                        __floats2half2_rn(vx, vy);
                } else {
                    const float* rp = Rres + (size_t)gm * HID + gn;
                    vx += rp[0]; vy += rp[1];
                    *(float2*)(Cf + (size_t)gm * ldc + gn) = make_float2(vx, vy);
                }
            }
        }
    }
}

// ---------------------------------------------------------------- Attention (flash, mma.sync tf32; unchanged)
__global__ __launch_bounds__(256, 2)
void attn_kernel(const int* __restrict__ lenp)
{
    extern __shared__ float sma[];
    float* Qs = sma;
    float* Ks = sma + 128 * AQ;
    float* Vs = Ks + 32 * AQ;
    float* Ps = Qs;

    int blk = blockIdx.x, h = blockIdx.y;
    int t = threadIdx.x, wid = t >> 5, lane = t & 31;
    int r = lane >> 2, cc = lane & 3;
    int q0  = blk * 128;
    int q0w = q0 + wid * 16;
    unsigned lm = ~((unsigned)(*lenp) - 1u);
    int qlo = q0w + r, qhi = qlo + 8;
    unsigned seqlo = (unsigned)qlo & lm, seqhi = (unsigned)qhi & lm;

    const float* Qg = g_qr + ((size_t)h * NTOK + q0) * DH;
    const float* Kg = g_kr + (size_t)h * NTOK * DH;
    const float* Vg = g_vr + (size_t)h * NTOK * DH;

    #pragma unroll
    for (int i = 0; i < 8; i++) {
        int f = t + i * 256;
        int row = f >> 4, c4 = f & 15;
        *(float4*)&Qs[row * AQ + c4 * 4] = *(const float4*)(Qg + (size_t)row * DH + c4 * 4);
    }
    __syncthreads();

    uint32_t qf[8][4];
    #pragma unroll
    for (int ks = 0; ks < 8; ks++) {
        const float* base = &Qs[(wid * 16 + r) * AQ + ks * 8 + cc];
        qf[ks][0] = __float_as_uint(base[0]);
        qf[ks][1] = __float_as_uint(base[8 * AQ]);
        qf[ks][2] = __float_as_uint(base[4]);
        qf[ks][3] = __float_as_uint(base[8 * AQ + 4]);
    }

    float o[8][4];
    #pragma unroll
    for (int i = 0; i < 8; i++)
        #pragma unroll
        for (int j = 0; j < 4; j++) o[i][j] = 0.f;
    float m_lo = -1e30f, m_hi = -1e30f, l_lo = 0.f, l_hi = 0.f;

    int kt0 = (q0 < 256) ? ((256 - q0) >> 5) : 0;

    for (int kt = kt0; kt < 12; kt++) {
        int kbase = q0 - 256 + kt * 32;
        __syncthreads();
        #pragma unroll
        for (int i = 0; i < 2; i++) {
            int f = t + i * 256;
            int row = f >> 4, c4 = f & 15;
            *(float4*)&Ks[row * AQ + c4 * 4] = *(const float4*)(Kg + (size_t)(kbase + row) * DH + c4 * 4);
            *(float4*)&Vs[row * AQ + c4 * 4] = *(const float4*)(Vg + (size_t)(kbase + row) * DH + c4 * 4);
        }
        __syncthreads();

        bool active = (kbase <= q0w + 15) && (q0w - (kbase + 31) < WIN);
        if (active) {
            float sc[4][4];
            #pragma unroll
            for (int nt = 0; nt < 4; nt++) {
                sc[nt][0] = sc[nt][1] = sc[nt][2] = sc[nt][3] = 0.f;
                #pragma unroll
                for (int ks = 0; ks < 8; ks++) {
                    const float* bb = &Ks[(nt * 8 + r) * AQ + ks * 8 + cc];
                    uint32_t bf[2] = { __float_as_uint(bb[0]), __float_as_uint(bb[4]) };
                    mma_tf32(sc[nt], qf[ks], bf);
                }
            }
            float tlo = -1e30f, thi = -1e30f;
            #pragma unroll
            for (int nt = 0; nt < 4; nt++) {
                #pragma unroll
                for (int b = 0; b < 2; b++) {
                    int ktok = kbase + nt * 8 + 2 * cc + b;
                    unsigned kseq = (unsigned)ktok & lm;
                    int dlo = qlo - ktok, dhi = qhi - ktok;
                    if (!(dlo >= 0 && dlo < WIN && kseq == seqlo)) sc[nt][b]     = -2e30f;
                    if (!(dhi >= 0 && dhi < WIN && kseq == seqhi)) sc[nt][2 + b] = -2e30f;
                    tlo = fmaxf(tlo, sc[nt][b]);
                    thi = fmaxf(thi, sc[nt][2 + b]);
                }
            }
            tlo = fmaxf(tlo, __shfl_xor_sync(0xffffffffu, tlo, 1));
            tlo = fmaxf(tlo, __shfl_xor_sync(0xffffffffu, tlo, 2));
            thi = fmaxf(thi, __shfl_xor_sync(0xffffffffu, thi, 1));
            thi = fmaxf(thi, __shfl_xor_sync(0xffffffffu, thi, 2));

            float mn_lo = fmaxf(m_lo, tlo), mn_hi = fmaxf(m_hi, thi);
            float co_lo = __expf(m_lo - mn_lo), co_hi = __expf(m_hi - mn_hi);
            m_lo = mn_lo; m_hi = mn_hi;
            l_lo *= co_lo; l_hi *= co_hi;
            #pragma unroll
            for (int i = 0; i < 8; i++) {
                o[i][0] *= co_lo; o[i][1] *= co_lo;
                o[i][2] *= co_hi; o[i][3] *= co_hi;
            }
            float* Pw = Ps + wid * 16 * PSTR;
            #pragma unroll
            for (int nt = 0; nt < 4; nt++) {
                float p0 = f2tf32_rna(__expf(sc[nt][0] - mn_lo));
                float p1 = f2tf32_rna(__expf(sc[nt][1] - mn_lo));
                float p2 = f2tf32_rna(__expf(sc[nt][2] - mn_hi));
                float p3 = f2tf32_rna(__expf(sc[nt][3] - mn_hi));
                l_lo += p0 + p1; l_hi += p2 + p3;
                Pw[r * PSTR + nt * 8 + 2 * cc]           = p0;
                Pw[r * PSTR + nt * 8 + 2 * cc + 1]       = p1;
                Pw[(r + 8) * PSTR + nt * 8 + 2 * cc]     = p2;
                Pw[(r + 8) * PSTR + nt * 8 + 2 * cc + 1] = p3;
            }
            __syncwarp();
            uint32_t pf[4][4];
            #pragma unroll
            for (int kk = 0; kk < 4; kk++) {
                const float* base = &Pw[r * PSTR + kk * 8 + cc];
                pf[kk][0] = __float_as_uint(base[0]);
                pf[kk][1] = __float_as_uint(base[8 * PSTR]);
                pf[kk][2] = __float_as_uint(base[4]);
                pf[kk][3] = __float_as_uint(base[8 * PSTR + 4]);
            }
            #pragma unroll
            for (int ntd = 0; ntd < 8; ntd++) {
                #pragma unroll
                for (int kk = 0; kk < 4; kk++) {
                    uint32_t bf[2] = {
                        __float_as_uint(Vs[(kk * 8 + cc) * AQ + ntd * 8 + r]),
                        __float_as_uint(Vs[(kk * 8 + cc + 4) * AQ + ntd * 8 + r]) };
                    mma_tf32(o[ntd], pf[kk], bf);
                }
            }
        }
    }

    l_lo += __shfl_xor_sync(0xffffffffu, l_lo, 1);
    l_lo += __shfl_xor_sync(0xffffffffu, l_lo, 2);
    l_hi += __shfl_xor_sync(0xffffffffu, l_hi, 1);
    l_hi += __shfl_xor_sync(0xffffffffu, l_hi, 2);
    float ilo = 1.0f / l_lo, ihi = 1.0f / l_hi;
    __half* out_lo = g_combh + (size_t)qlo * COMBW + h * DH;
    __half* out_hi = g_combh + (size_t)qhi * COMBW + h * DH;
    #pragma unroll
    for (int ntd = 0; ntd < 8; ntd++) {
        int gn = ntd * 8 + 2 * cc;
        *(__half2*)(out_lo + gn) = __floats2half2_rn(o[ntd][0] * ilo, o[ntd][1] * ilo);
        *(__half2*)(out_hi + gn) = __floats2half2_rn(o[ntd][2] * ihi, o[ntd][3] * ihi);
    }
}

// ---------------------------------------------------------------- launch
extern "C" void kernel_launch(void* const* d_in, const int* in_sizes, int n_in,
                              void* d_out, int out_size)
{
    (void)in_sizes; (void)n_in; (void)out_size;
    const float* x        = (const float*)d_in[0];
    const float* pos_sin  = (const float*)d_in[2];
    const float* pos_cos  = (const float*)d_in[3];
    const float* ln_scale = (const float*)d_in[4];
    const float* ln_off   = (const float*)d_in[5];
    const float* w_in     = (const float*)d_in[6];
    const float* b_in     = (const float*)d_in[7];
    const float* w_out    = (const float*)d_in[8];
    const float* b_out    = (const float*)d_in[9];
    const int*   lenp     = (const int*)d_in[10];
    float* out = (float*)d_out;

    static float  *p_xn = nullptr;
    static __half *p_xnh = nullptr, *p_combh = nullptr, *p_wt1h = nullptr, *p_wt2h = nullptr;
    static cudaStream_t s1 = nullptr;
    static cudaEvent_t e0 = nullptr, eT = nullptr, eLN = nullptr, eF = nullptr;
    if (!p_xn) {
        cudaGetSymbolAddress((void**)&p_xn,    g_xn);
        cudaGetSymbolAddress((void**)&p_xnh,   g_xnh);
        cudaGetSymbolAddress((void**)&p_combh, g_combh);
        cudaGetSymbolAddress((void**)&p_wt1h,  g_wt1h);
        cudaGetSymbolAddress((void**)&p_wt2h,  g_wt2h);
        cudaFuncSetAttribute(hgemm_kernel,
                             cudaFuncAttributeMaxDynamicSharedMemorySize, DSMEM_BYTES);
        cudaFuncSetAttribute(attn_kernel,
                             cudaFuncAttributeMaxDynamicSharedMemorySize, ATTN_SMEM);
        cudaStreamCreateWithFlags(&s1, cudaStreamNonBlocking);
        cudaEventCreateWithFlags(&e0,  cudaEventDisableTiming);
        cudaEventCreateWithFlags(&eT,  cudaEventDisableTiming);
        cudaEventCreateWithFlags(&eLN, cudaEventDisableTiming);
        cudaEventCreateWithFlags(&eF,  cudaEventDisableTiming);
    }

    // fork s1 from the (captured) default stream
    cudaEventRecord(e0, 0);
    cudaStreamWaitEvent(s1, e0, 0);

    // s1: weight transposes (f32 -> fp16); s0: layernorm (f32 + fp16)
    transpose_kernel<<<dim3(MIDW / 32, HID / 32),   dim3(32, 8), 0, s1>>>(w_in,  p_wt1h, HID,   MIDW);
    transpose_kernel<<<dim3(HID / 32,  COMBW / 32), dim3(32, 8), 0, s1>>>(w_out, p_wt2h, COMBW, HID);
    ln_kernel<<<NTOK, 256>>>(x, ln_scale, ln_off);
    cudaEventRecord(eLN, 0);

    // s0: QKV GEMM + fused RoPE -> g_qr/g_kr/g_vr (needs wt1h)
    cudaEventRecord(eT, s1);
    cudaStreamWaitEvent(0, eT, 0);
    hgemm_kernel<<<dim3(QKVW / 128, NTOK / 128), 256, DSMEM_BYTES>>>(
        p_xnh, HID, p_wt1h, HID, b_in, nullptr, nullptr, nullptr, 0,
        HID, 2, pos_sin, pos_cos);

    // s1: FF GEMM + gelu -> combh[:, 768:] (needs ln) — overlaps QKV + attn
    cudaStreamWaitEvent(s1, eLN, 0);
    hgemm_kernel<<<dim3(INTER / 128, NTOK / 128), 256, DSMEM_BYTES, s1>>>(
        p_xnh, HID, p_wt1h + (size_t)QKVW * HID, HID, b_in + QKVW, nullptr,
        nullptr, p_combh + HID, COMBW, HID, 1, nullptr, nullptr);
    cudaEventRecord(eF, s1);

    // s0: flash attention -> combh[:, :768]
    attn_kernel<<<dim3(NTOK / 128, NH), 256, ATTN_SMEM>>>(lenp);

    // join, then s0: out = xn + combh @ w_out + b_out  (f32 residual/output)
    cudaStreamWaitEvent(0, eF, 0);
    hgemm_kernel<<<dim3(HID / 128, NTOK / 128), 256, DSMEM_BYTES>>>(
        p_combh, COMBW, p_wt2h, COMBW, b_out, p_xn, out, nullptr, HID,
        COMBW, 0, nullptr, nullptr);
}

// round 17
// speedup vs baseline: 1.8235x; 1.0500x over previous
#include <cuda_runtime.h>
#include <cuda_fp16.h>
#include <cfloat>
#include <cstddef>
#include <cstdint>

#define HID   768
#define INTER 3072
#define NH    12
#define DH    64
#define NTOK  16384
#define WIN   256
#define MIDW  (3*HID + INTER)   // 5376
#define QKVW  (3*HID)           // 2304
#define COMBW (HID + INTER)     // 3840

#define ASTRH 72                      // fp16 gemm smem row stride (halfs), 144B
#define TILE_BYTES (128 * ASTRH * 2)  // 18432 per operand tile (128 x 64 halfs + pad)
#define STAGE_BYTES (2 * TILE_BYTES)  // 36864
#define GSTAGES 3
#define DSMEM_BYTES (GSTAGES * STAGE_BYTES) // 110592; 2 CTAs/SM = 216 KB

#define AQ   68                       // attn Q/K/V smem row stride (floats)
#define PSTR 36                       // attn probs smem row stride
#define ATTN_SMEM ((128*AQ + 32*AQ + 32*AQ) * 4)   // 52224 B

// Scratch (device globals: allocation inside kernel_launch is forbidden)
__device__ float  g_xn  [(size_t)NTOK * HID];     // f32 xn (residual)
__device__ __half g_xnh [(size_t)NTOK * HID];     // fp16 xn (GEMM A)
__device__ __half g_combh[(size_t)NTOK * COMBW];  // fp16 [attn | gelu(ff)]
__device__ __half g_wt1h[(size_t)MIDW * HID];     // fp16 w_in^T
__device__ __half g_wt2h[(size_t)HID * COMBW];    // fp16 w_out^T
__device__ float  g_qr  [(size_t)NH * NTOK * DH]; // tf32-rounded RoPE'd Q (scaled)
__device__ float  g_kr  [(size_t)NH * NTOK * DH]; // tf32-rounded RoPE'd K
__device__ float  g_vr  [(size_t)NH * NTOK * DH]; // tf32-rounded V

// ---------------------------------------------------------------- helpers
__device__ __forceinline__ uint32_t smem_u32(const void* p) {
    uint32_t a;
    asm("{ .reg .u64 t; cvta.to.shared.u64 t, %1; cvt.u32.u64 %0, t; }"
        : "=r"(a) : "l"(p));
    return a;
}
__device__ __forceinline__ float f2tf32_rna(float x) {
    uint32_t u;
    asm("cvt.rna.tf32.f32 %0, %1;" : "=r"(u) : "f"(x));
    return __uint_as_float(u);
}
__device__ __forceinline__ void cp_async16(uint32_t dst, const void* src) {
    asm volatile("cp.async.cg.shared.global [%0], [%1], 16;"
                 :: "r"(dst), "l"(src) : "memory");
}
__device__ __forceinline__ void cp_commit() {
    asm volatile("cp.async.commit_group;" ::: "memory");
}
__device__ __forceinline__ void cp_wait1() {
    asm volatile("cp.async.wait_group 1;" ::: "memory");
}
__device__ __forceinline__ void cp_wait0() {
    asm volatile("cp.async.wait_group 0;" ::: "memory");
}
__device__ __forceinline__ void ldsm_x4(uint32_t* r, uint32_t addr) {
    asm volatile("ldmatrix.sync.aligned.m8n8.x4.shared.b16 {%0,%1,%2,%3}, [%4];"
                 : "=r"(r[0]), "=r"(r[1]), "=r"(r[2]), "=r"(r[3]) : "r"(addr));
}
// fp16 HMMA: D(f32) += A(f16) x B(f16), m16n8k16
__device__ __forceinline__ void mma_f16(float* d, const uint32_t* a, const uint32_t* b) {
    asm volatile(
        "mma.sync.aligned.m16n8k16.row.col.f32.f16.f16.f32 "
        "{%0,%1,%2,%3}, {%4,%5,%6,%7}, {%8,%9}, {%0,%1,%2,%3};"
        : "+f"(d[0]), "+f"(d[1]), "+f"(d[2]), "+f"(d[3])
        : "r"(a[0]), "r"(a[1]), "r"(a[2]), "r"(a[3]), "r"(b[0]), "r"(b[1]));
}
// tf32 HMMA (attention)
__device__ __forceinline__ void mma_tf32(float* d, const uint32_t* a, const uint32_t* b) {
    asm volatile(
        "mma.sync.aligned.m16n8k8.row.col.f32.tf32.tf32.f32 "
        "{%0,%1,%2,%3}, {%4,%5,%6,%7}, {%8,%9}, {%0,%1,%2,%3};"
        : "+f"(d[0]), "+f"(d[1]), "+f"(d[2]), "+f"(d[3])
        : "r"(a[0]), "r"(a[1]), "r"(a[2]), "r"(a[3]), "r"(b[0]), "r"(b[1]));
}

// ---------------------------------------------------------------- GELU (tanh approx = jax default)
__device__ __forceinline__ float gelu_f(float x) {
    float x3 = x * x * x;
    return 0.5f * x * (1.0f + tanhf(0.7978845608028654f * (x + 0.044715f * x3)));
}

// ---------------------------------------------------------------- LayerNorm (f32 + fp16 outputs)
__global__ void ln_kernel(const float* __restrict__ x,
                          const float* __restrict__ gam,
                          const float* __restrict__ bet)
{
    int row = blockIdx.x;
    int t   = threadIdx.x;
    const float* xr = x + (size_t)row * HID;
    float v0 = xr[t], v1 = xr[t + 256], v2 = xr[t + 512];
    float s  = v0 + v1 + v2;
    float s2 = v0*v0 + v1*v1 + v2*v2;
    #pragma unroll
    for (int o = 16; o > 0; o >>= 1) {
        s  += __shfl_xor_sync(0xffffffffu, s,  o);
        s2 += __shfl_xor_sync(0xffffffffu, s2, o);
    }
    __shared__ float red0[8], red1[8];
    __shared__ float stat[2];
    int w = t >> 5, l = t & 31;
    if (l == 0) { red0[w] = s; red1[w] = s2; }
    __syncthreads();
    if (t == 0) {
        float ts = 0.f, ts2 = 0.f;
        #pragma unroll
        for (int i = 0; i < 8; i++) { ts += red0[i]; ts2 += red1[i]; }
        float mu  = ts * (1.0f / HID);
        float var = ts2 * (1.0f / HID) - mu * mu;
        stat[0] = mu;
        stat[1] = rsqrtf(var + 1e-5f);
    }
    __syncthreads();
    float mu = stat[0], inv = stat[1];
    float* o  = g_xn  + (size_t)row * HID;
    __half* oh = g_xnh + (size_t)row * HID;
    float r0 = (v0 - mu) * inv * gam[t]       + bet[t];
    float r1 = (v1 - mu) * inv * gam[t + 256] + bet[t + 256];
    float r2 = (v2 - mu) * inv * gam[t + 512] + bet[t + 512];
    o[t] = r0;  o[t + 256] = r1;  o[t + 512] = r2;
    oh[t] = __float2half_rn(r0);
    oh[t + 256] = __float2half_rn(r1);
    oh[t + 512] = __float2half_rn(r2);
}

// ---------------------------------------------------------------- Transpose f32 -> fp16 (R x C -> C x R)
__global__ void transpose_kernel(const float* __restrict__ in, __half* __restrict__ out,
                                 int R, int C)
{
    __shared__ float tile[32][33];
    int bx = blockIdx.x * 32, by = blockIdx.y * 32;
    int tx = threadIdx.x, ty = threadIdx.y;
    #pragma unroll
    for (int i = 0; i < 32; i += 8)
        tile[ty + i][tx] = in[(size_t)(by + ty + i) * C + bx + tx];
    __syncthreads();
    #pragma unroll
    for (int i = 0; i < 32; i += 8)
        out[(size_t)(bx + ty + i) * R + by + tx] = __float2half_rn(tile[tx][ty + i]);
}

// ---------------------------------------------------------------- fp16 HMMA GEMM (ldmatrix fragment feed)
// 128x128 CTA tile, 8 warps, 64x32 warp tile, 3-stage ring, K-stage = 64.
// epi: 0 = bias + R(f32) residual -> Cf(f32) ; 1 = gelu(bias) -> Ch(fp16) ;
//      2 = QKV: RoPE+scale, tf32-round -> g_qr/g_kr/g_vr
__global__ __launch_bounds__(256, 2)
void hgemm_kernel(const __half* __restrict__ A, int lda,
                  const __half* __restrict__ Bt, int ldb,
                  const float* __restrict__ bias,
                  const float* __restrict__ Rres,
                  float* __restrict__ Cf, __half* __restrict__ Ch, int ldc,
                  int K, int epi,
                  const float* __restrict__ psin,
                  const float* __restrict__ pcos)
{
    extern __shared__ __half smh[];
    uint32_t sbase = smem_u32(smh);

    int t = threadIdx.x;
    int wid = t >> 5, lane = t & 31;
    int warp_m = (wid >> 2) * 64, warp_n = (wid & 3) * 32;
    int bm = blockIdx.y * 128, bn = blockIdx.x * 128;
    int r = lane >> 2, c = lane & 3;

    // ldmatrix per-lane address components
    int a_row  = warp_m + (lane & 15);          // + mt*16
    int a_koff = (lane >> 4) * 8;               // k tile select
    int b_n    = warp_n + (lane >> 4) * 8 + (lane & 7);  // + ntp*16
    int b_koff = ((lane >> 3) & 1) * 8;

    const __half* Ag = A  + (size_t)bm * lda;
    const __half* Bg = Bt + (size_t)bn * ldb;

    float acc[16][4];
    #pragma unroll
    for (int i = 0; i < 16; i++)
        #pragma unroll
        for (int j = 0; j < 4; j++) acc[i][j] = 0.f;

    int cm[4], ck[4];
    #pragma unroll
    for (int i = 0; i < 4; i++) {
        int id = t + i * 256;
        cm[i] = id >> 3;              // row 0..127
        ck[i] = (id & 7) * 8;         // half offset within 64-half row
    }

    auto load_stage = [&](int buf, int kbase) {
        uint32_t ab = sbase + (uint32_t)buf * STAGE_BYTES;
        uint32_t bb = ab + TILE_BYTES;
        #pragma unroll
        for (int i = 0; i < 4; i++) {
            cp_async16(ab + (uint32_t)(cm[i] * ASTRH + ck[i]) * 2u,
                       Ag + (size_t)cm[i] * lda + kbase + ck[i]);
            cp_async16(bb + (uint32_t)(cm[i] * ASTRH + ck[i]) * 2u,
                       Bg + (size_t)cm[i] * ldb + kbase + ck[i]);
        }
    };

    int S = K / 64;   // K % 64 == 0 at all call sites (768, 3840)
    load_stage(0, 0);
    cp_commit();
    load_stage(1, 64);
    cp_commit();

    int buf = 0;
    for (int s = 0; s < S; s++) {
        if (s + 1 < S) cp_wait1();
        else           cp_wait0();
        __syncthreads();
        int nxt = s + 2;
        if (nxt < S) {
            int nbuf = buf + 2; if (nbuf >= GSTAGES) nbuf -= GSTAGES;
            load_stage(nbuf, nxt * 64);
            cp_commit();
        }

        uint32_t ab = sbase + (uint32_t)buf * STAGE_BYTES;
        uint32_t bb = ab + TILE_BYTES;
        uint32_t abase = ab + (uint32_t)(a_row * ASTRH + a_koff) * 2u;
        uint32_t bbase = bb + (uint32_t)(b_n * ASTRH + b_koff) * 2u;
        #pragma unroll
        for (int ks = 0; ks < 4; ks++) {
            int k0 = ks * 16;
            uint32_t af[4][4];
            #pragma unroll
            for (int mt = 0; mt < 4; mt++)
                ldsm_x4(af[mt], abase + (uint32_t)(mt * 16 * ASTRH + k0) * 2u);
            uint32_t bf[4][2];
            #pragma unroll
            for (int ntp = 0; ntp < 2; ntp++) {
                uint32_t btmp[4];
                ldsm_x4(btmp, bbase + (uint32_t)(ntp * 16 * ASTRH + k0) * 2u);
                bf[2 * ntp][0]     = btmp[0];
                bf[2 * ntp][1]     = btmp[1];
                bf[2 * ntp + 1][0] = btmp[2];
                bf[2 * ntp + 1][1] = btmp[3];
            }
            #pragma unroll
            for (int mt = 0; mt < 4; mt++)
                #pragma unroll
                for (int nt = 0; nt < 4; nt++)
                    mma_f16(acc[mt * 4 + nt], af[mt], bf[nt]);
        }
        if (++buf == GSTAGES) buf = 0;
    }

    // ---- epilogue (C frag map: c0:(r,2c) c1:(r,2c+1) c2:(r+8,2c) c3:(r+8,2c+1))
    #pragma unroll
    for (int mt = 0; mt < 4; mt++) {
        #pragma unroll
        for (int nt = 0; nt < 4; nt++) {
            float* a4 = acc[mt * 4 + nt];
            int gm0 = bm + warp_m + mt * 16 + r;
            int gn  = bn + warp_n + nt * 8 + c * 2;
            float bx = bias[gn], by = bias[gn + 1];
            #pragma unroll
            for (int half = 0; half < 2; half++) {
                int gm = gm0 + half * 8;
                float vx = a4[half * 2 + 0] + bx;
                float vy = a4[half * 2 + 1] + by;
                if (epi == 2) {
                    int sec = gn / HID;            // 0=q 1=k 2=v
                    int rem = gn - sec * HID;
                    int h = rem >> 6, d = rem & 63;
                    size_t off = ((size_t)h * NTOK + gm) * DH + d;
                    if (sec == 2) {
                        *(float2*)(g_vr + off) =
                            make_float2(f2tf32_rna(vx), f2tf32_rna(vy));
                    } else {
                        float2 sv = *(const float2*)(psin + (size_t)gm * DH + d);
                        float2 cv = *(const float2*)(pcos + (size_t)gm * DH + d);
                        float ox = vx * cv.x - vy * sv.x;
                        float oy = vy * cv.y + vx * sv.y;
                        if (sec == 0) {
                            ox *= 0.125f; oy *= 0.125f;
                            *(float2*)(g_qr + off) =
                                make_float2(f2tf32_rna(ox), f2tf32_rna(oy));
                        } else {
                            *(float2*)(g_kr + off) =
                                make_float2(f2tf32_rna(ox), f2tf32_rna(oy));
                        }
                    }
                } else if (epi == 1) {
                    vx = gelu_f(vx); vy = gelu_f(vy);
                    *(__half2*)(Ch + (size_t)gm * ldc + gn) =
                        __floats2half2_rn(vx, vy);
                } else {
                    const float* rp = Rres + (size_t)gm * HID + gn;
                    vx += rp[0]; vy += rp[1];
                    *(float2*)(Cf + (size_t)gm * ldc + gn) = make_float2(vx, vy);
                }
            }
        }
    }
}

// ---------------------------------------------------------------- Attention (flash, mma.sync tf32; unchanged)
__global__ __launch_bounds__(256, 2)
void attn_kernel(const int* __restrict__ lenp)
{
    extern __shared__ float sma[];
    float* Qs = sma;
    float* Ks = sma + 128 * AQ;
    float* Vs = Ks + 32 * AQ;
    float* Ps = Qs;

    int blk = blockIdx.x, h = blockIdx.y;
    int t = threadIdx.x, wid = t >> 5, lane = t & 31;
    int r = lane >> 2, cc = lane & 3;
    int q0  = blk * 128;
    int q0w = q0 + wid * 16;
    unsigned lm = ~((unsigned)(*lenp) - 1u);
    int qlo = q0w + r, qhi = qlo + 8;
    unsigned seqlo = (unsigned)qlo & lm, seqhi = (unsigned)qhi & lm;

    const float* Qg = g_qr + ((size_t)h * NTOK + q0) * DH;
    const float* Kg = g_kr + (size_t)h * NTOK * DH;
    const float* Vg = g_vr + (size_t)h * NTOK * DH;

    #pragma unroll
    for (int i = 0; i < 8; i++) {
        int f = t + i * 256;
        int row = f >> 4, c4 = f & 15;
        *(float4*)&Qs[row * AQ + c4 * 4] = *(const float4*)(Qg + (size_t)row * DH + c4 * 4);
    }
    __syncthreads();

    uint32_t qf[8][4];
    #pragma unroll
    for (int ks = 0; ks < 8; ks++) {
        const float* base = &Qs[(wid * 16 + r) * AQ + ks * 8 + cc];
        qf[ks][0] = __float_as_uint(base[0]);
        qf[ks][1] = __float_as_uint(base[8 * AQ]);
        qf[ks][2] = __float_as_uint(base[4]);
        qf[ks][3] = __float_as_uint(base[8 * AQ + 4]);
    }

    float o[8][4];
    #pragma unroll
    for (int i = 0; i < 8; i++)
        #pragma unroll
        for (int j = 0; j < 4; j++) o[i][j] = 0.f;
    float m_lo = -1e30f, m_hi = -1e30f, l_lo = 0.f, l_hi = 0.f;

    int kt0 = (q0 < 256) ? ((256 - q0) >> 5) : 0;

    for (int kt = kt0; kt < 12; kt++) {
        int kbase = q0 - 256 + kt * 32;
        __syncthreads();
        #pragma unroll
        for (int i = 0; i < 2; i++) {
            int f = t + i * 256;
            int row = f >> 4, c4 = f & 15;
            *(float4*)&Ks[row * AQ + c4 * 4] = *(const float4*)(Kg + (size_t)(kbase + row) * DH + c4 * 4);
            *(float4*)&Vs[row * AQ + c4 * 4] = *(const float4*)(Vg + (size_t)(kbase + row) * DH + c4 * 4);
        }
        __syncthreads();

        bool active = (kbase <= q0w + 15) && (q0w - (kbase + 31) < WIN);
        if (active) {
            float sc[4][4];
            #pragma unroll
            for (int nt = 0; nt < 4; nt++) {
                sc[nt][0] = sc[nt][1] = sc[nt][2] = sc[nt][3] = 0.f;
                #pragma unroll
                for (int ks = 0; ks < 8; ks++) {
                    const float* bb = &Ks[(nt * 8 + r) * AQ + ks * 8 + cc];
                    uint32_t bf[2] = { __float_as_uint(bb[0]), __float_as_uint(bb[4]) };
                    mma_tf32(sc[nt], qf[ks], bf);
                }
            }
            float tlo = -1e30f, thi = -1e30f;
            #pragma unroll
            for (int nt = 0; nt < 4; nt++) {
                #pragma unroll
                for (int b = 0; b < 2; b++) {
                    int ktok = kbase + nt * 8 + 2 * cc + b;
                    unsigned kseq = (unsigned)ktok & lm;
                    int dlo = qlo - ktok, dhi = qhi - ktok;
                    if (!(dlo >= 0 && dlo < WIN && kseq == seqlo)) sc[nt][b]     = -2e30f;
                    if (!(dhi >= 0 && dhi < WIN && kseq == seqhi)) sc[nt][2 + b] = -2e30f;
                    tlo = fmaxf(tlo, sc[nt][b]);
                    thi = fmaxf(thi, sc[nt][2 + b]);
                }
            }
            tlo = fmaxf(tlo, __shfl_xor_sync(0xffffffffu, tlo, 1));
            tlo = fmaxf(tlo, __shfl_xor_sync(0xffffffffu, tlo, 2));
            thi = fmaxf(thi, __shfl_xor_sync(0xffffffffu, thi, 1));
            thi = fmaxf(thi, __shfl_xor_sync(0xffffffffu, thi, 2));

            float mn_lo = fmaxf(m_lo, tlo), mn_hi = fmaxf(m_hi, thi);
            float co_lo = __expf(m_lo - mn_lo), co_hi = __expf(m_hi - mn_hi);
            m_lo = mn_lo; m_hi = mn_hi;
            l_lo *= co_lo; l_hi *= co_hi;
            #pragma unroll
            for (int i = 0; i < 8; i++) {
                o[i][0] *= co_lo; o[i][1] *= co_lo;
                o[i][2] *= co_hi; o[i][3] *= co_hi;
            }
            float* Pw = Ps + wid * 16 * PSTR;
            #pragma unroll
            for (int nt = 0; nt < 4; nt++) {
                float p0 = f2tf32_rna(__expf(sc[nt][0] - mn_lo));
                float p1 = f2tf32_rna(__expf(sc[nt][1] - mn_lo));
                float p2 = f2tf32_rna(__expf(sc[nt][2] - mn_hi));
                float p3 = f2tf32_rna(__expf(sc[nt][3] - mn_hi));
                l_lo += p0 + p1; l_hi += p2 + p3;
                Pw[r * PSTR + nt * 8 + 2 * cc]           = p0;
                Pw[r * PSTR + nt * 8 + 2 * cc + 1]       = p1;
                Pw[(r + 8) * PSTR + nt * 8 + 2 * cc]     = p2;
                Pw[(r + 8) * PSTR + nt * 8 + 2 * cc + 1] = p3;
            }
            __syncwarp();
            uint32_t pf[4][4];
            #pragma unroll
            for (int kk = 0; kk < 4; kk++) {
                const float* base = &Pw[r * PSTR + kk * 8 + cc];
                pf[kk][0] = __float_as_uint(base[0]);
                pf[kk][1] = __float_as_uint(base[8 * PSTR]);
                pf[kk][2] = __float_as_uint(base[4]);
                pf[kk][3] = __float_as_uint(base[8 * PSTR + 4]);
            }
            #pragma unroll
            for (int ntd = 0; ntd < 8; ntd++) {
                #pragma unroll
                for (int kk = 0; kk < 4; kk++) {
                    uint32_t bf[2] = {
                        __float_as_uint(Vs[(kk * 8 + cc) * AQ + ntd * 8 + r]),
                        __float_as_uint(Vs[(kk * 8 + cc + 4) * AQ + ntd * 8 + r]) };
                    mma_tf32(o[ntd], pf[kk], bf);
                }
            }
        }
    }

    l_lo += __shfl_xor_sync(0xffffffffu, l_lo, 1);
    l_lo += __shfl_xor_sync(0xffffffffu, l_lo, 2);
    l_hi += __shfl_xor_sync(0xffffffffu, l_hi, 1);
    l_hi += __shfl_xor_sync(0xffffffffu, l_hi, 2);
    float ilo = 1.0f / l_lo, ihi = 1.0f / l_hi;
    __half* out_lo = g_combh + (size_t)qlo * COMBW + h * DH;
    __half* out_hi = g_combh + (size_t)qhi * COMBW + h * DH;
    #pragma unroll
    for (int ntd = 0; ntd < 8; ntd++) {
        int gn = ntd * 8 + 2 * cc;
        *(__half2*)(out_lo + gn) = __floats2half2_rn(o[ntd][0] * ilo, o[ntd][1] * ilo);
        *(__half2*)(out_hi + gn) = __floats2half2_rn(o[ntd][2] * ihi, o[ntd][3] * ihi);
    }
}

// ---------------------------------------------------------------- launch
extern "C" void kernel_launch(void* const* d_in, const int* in_sizes, int n_in,
                              void* d_out, int out_size)
{
    (void)in_sizes; (void)n_in; (void)out_size;
    const float* x        = (const float*)d_in[0];
    const float* pos_sin  = (const float*)d_in[2];
    const float* pos_cos  = (const float*)d_in[3];
    const float* ln_scale = (const float*)d_in[4];
    const float* ln_off   = (const float*)d_in[5];
    const float* w_in     = (const float*)d_in[6];
    const float* b_in     = (const float*)d_in[7];
    const float* w_out    = (const float*)d_in[8];
    const float* b_out    = (const float*)d_in[9];
    const int*   lenp     = (const int*)d_in[10];
    float* out = (float*)d_out;

    static float  *p_xn = nullptr;
    static __half *p_xnh = nullptr, *p_combh = nullptr, *p_wt1h = nullptr, *p_wt2h = nullptr;
    static cudaStream_t s1 = nullptr;
    static cudaEvent_t e0 = nullptr, eT = nullptr, eLN = nullptr, eF = nullptr;
    if (!p_xn) {
        cudaGetSymbolAddress((void**)&p_xn,    g_xn);
        cudaGetSymbolAddress((void**)&p_xnh,   g_xnh);
        cudaGetSymbolAddress((void**)&p_combh, g_combh);
        cudaGetSymbolAddress((void**)&p_wt1h,  g_wt1h);
        cudaGetSymbolAddress((void**)&p_wt2h,  g_wt2h);
        cudaFuncSetAttribute(hgemm_kernel,
                             cudaFuncAttributeMaxDynamicSharedMemorySize, DSMEM_BYTES);
        cudaFuncSetAttribute(attn_kernel,
                             cudaFuncAttributeMaxDynamicSharedMemorySize, ATTN_SMEM);
        cudaStreamCreateWithFlags(&s1, cudaStreamNonBlocking);
        cudaEventCreateWithFlags(&e0,  cudaEventDisableTiming);
        cudaEventCreateWithFlags(&eT,  cudaEventDisableTiming);
        cudaEventCreateWithFlags(&eLN, cudaEventDisableTiming);
        cudaEventCreateWithFlags(&eF,  cudaEventDisableTiming);
    }

    // fork s1 from the (captured) default stream
    cudaEventRecord(e0, 0);
    cudaStreamWaitEvent(s1, e0, 0);

    // s1: weight transposes (f32 -> fp16); s0: layernorm (f32 + fp16)
    transpose_kernel<<<dim3(MIDW / 32, HID / 32),   dim3(32, 8), 0, s1>>>(w_in,  p_wt1h, HID,   MIDW);
    transpose_kernel<<<dim3(HID / 32,  COMBW / 32), dim3(32, 8), 0, s1>>>(w_out, p_wt2h, COMBW, HID);
    ln_kernel<<<NTOK, 256>>>(x, ln_scale, ln_off);
    cudaEventRecord(eLN, 0);

    // s0: QKV GEMM + fused RoPE -> g_qr/g_kr/g_vr (needs wt1h)
    cudaEventRecord(eT, s1);
    cudaStreamWaitEvent(0, eT, 0);
    hgemm_kernel<<<dim3(QKVW / 128, NTOK / 128), 256, DSMEM_BYTES>>>(
        p_xnh, HID, p_wt1h, HID, b_in, nullptr, nullptr, nullptr, 0,
        HID, 2, pos_sin, pos_cos);

    // s1: FF GEMM + gelu -> combh[:, 768:] (needs ln) — overlaps QKV + attn
    cudaStreamWaitEvent(s1, eLN, 0);
    hgemm_kernel<<<dim3(INTER / 128, NTOK / 128), 256, DSMEM_BYTES, s1>>>(
        p_xnh, HID, p_wt1h + (size_t)QKVW * HID, HID, b_in + QKVW, nullptr,
        nullptr, p_combh + HID, COMBW, HID, 1, nullptr, nullptr);
    cudaEventRecord(eF, s1);

    // s0: flash attention -> combh[:, :768]
    attn_kernel<<<dim3(NTOK / 128, NH), 256, ATTN_SMEM>>>(lenp);

    // join, then s0: out = xn + combh @ w_out + b_out  (f32 residual/output)
    cudaStreamWaitEvent(0, eF, 0);
    hgemm_kernel<<<dim3(HID / 128, NTOK / 128), 256, DSMEM_BYTES>>>(
        p_combh, COMBW, p_wt2h, COMBW, b_out, p_xn, out, nullptr, HID,
        COMBW, 0, nullptr, nullptr);
}